// round 11
// baseline (speedup 1.0000x reference)
#include <cuda_runtime.h>
#include <cuda_bf16.h>
#include <cstdint>
#include <cstddef>

#define B_   16
#define NPT  4096
#define SPT  1024
#define D1_  256
#define D2_  128
#define CIN  384
#define CO   256
#define NS   (B_*NPT)   // 65536

// ---------------------------------------------------------------------------
// Scratch
// ---------------------------------------------------------------------------
__device__ float         g_p2t[B_ * SPT * D2_];
__device__ __nv_bfloat16 g_x1h[(size_t)NS * CIN];
__device__ __nv_bfloat16 g_x1l[(size_t)NS * CIN];
__device__ __nv_bfloat16 g_x2h[(size_t)NS * CO];
__device__ __nv_bfloat16 g_x2l[(size_t)NS * CO];
__device__ float         g_y1[(size_t)NS * CO];     // y1, then reused as y2
__device__ __nv_bfloat16 g_w1h[CO * CIN], g_w1l[CO * CIN];
__device__ __nv_bfloat16 g_w2h[CO * CO],  g_w2l[CO * CO];
__device__ float g_psum[256 * 256], g_psq[256 * 256]; // [rowblock][channel] partials
__device__ float g_a1[CO], g_b1[CO], g_a2[CO], g_b2[CO];
__device__ float4 g_nnw4[NS];   // 3 normalized weights per query
__device__ int4   g_nni4[NS];   // 3 neighbor indices per query

__device__ __forceinline__ uint32_t smem_u32(const void* p) {
    uint32_t a;
    asm("{ .reg .u64 t; cvta.to.shared.u64 t, %1; cvt.u32.u64 %0, t; }" : "=r"(a) : "l"(p));
    return a;
}
__device__ __forceinline__ void split_bf16(float a, uint32_t& h, uint32_t& l) {
    __nv_bfloat16 hb = __float2bfloat16(a);
    __nv_bfloat16 lb = __float2bfloat16(a - __bfloat162float(hb));
    h = (uint32_t)__bfloat16_as_ushort(hb);
    l = (uint32_t)__bfloat16_as_ushort(lb);
}

// ---------------------------------------------------------------------------
// W split
// ---------------------------------------------------------------------------
__global__ void k_wsplit(const float* __restrict__ W1, const float* __restrict__ W2) {
    const int i = blockIdx.x * 256 + threadIdx.x;
    uint32_t h, l;
    if (i < CO * CIN) {
        split_bf16(W1[i], h, l);
        g_w1h[i] = __ushort_as_bfloat16((unsigned short)h);
        g_w1l[i] = __ushort_as_bfloat16((unsigned short)l);
    } else {
        const int j = i - CO * CIN;
        split_bf16(W2[j], h, l);
        g_w2h[j] = __ushort_as_bfloat16((unsigned short)h);
        g_w2l[j] = __ushort_as_bfloat16((unsigned short)l);
    }
}

// ---------------------------------------------------------------------------
// transpose points2 [B,D2,S] -> g_p2t [B,S,D2]
// ---------------------------------------------------------------------------
__global__ void k_tp2(const float* __restrict__ p2) {
    __shared__ float t[32][33];
    const int b = blockIdx.z, c0 = blockIdx.y * 32, s0 = blockIdx.x * 32;
    const int tx = threadIdx.x, ty = threadIdx.y;
#pragma unroll
    for (int i = 0; i < 4; i++)
        t[ty + i * 8][tx] = p2[((size_t)b * D2_ + c0 + ty + i * 8) * SPT + s0 + tx];
    __syncthreads();
#pragma unroll
    for (int i = 0; i < 4; i++)
        g_p2t[((size_t)b * SPT + s0 + ty + i * 8) * D2_ + c0 + tx] = t[tx][ty + i * 8];
}

// ---------------------------------------------------------------------------
// transpose+split points1 [B,256,N] -> X1 cols [0,256)
// ---------------------------------------------------------------------------
__global__ void k_tp1(const float* __restrict__ p1) {
    __shared__ float t[32][33];
    const int b = blockIdx.z, c0 = blockIdx.y * 32, n0 = blockIdx.x * 32;
    const int tx = threadIdx.x, ty = threadIdx.y;
    const int tid = ty * 32 + tx;
#pragma unroll
    for (int i = 0; i < 4; i++)
        t[ty + i * 8][tx] = p1[((size_t)b * D1_ + c0 + ty + i * 8) * NPT + n0 + tx];
    __syncthreads();
#pragma unroll
    for (int w = 0; w < 2; w++) {
        const int v = w * 256 + tid;
        const int n = v >> 4, u = v & 15;
        uint32_t h0, l0, h1, l1;
        split_bf16(t[2 * u][n], h0, l0);
        split_bf16(t[2 * u + 1][n], h1, l1);
        const size_t a = (size_t)(b * NPT + n0 + n) * CIN + c0 + 2 * u;
        *(uint32_t*)(g_x1h + a) = h0 | (h1 << 16);
        *(uint32_t*)(g_x1l + a) = l0 | (l1 << 16);
    }
}

// ---------------------------------------------------------------------------
// k_nn: 4-way split-S 3-NN, 2 queries per thread (shared LDS + loop overhead).
// 256 threads = 4 parts x 64 lanes; each thread scans 256 refs for queries
// q and q+64; part 0 merges the 4 sorted triples per query.
// ---------------------------------------------------------------------------
__global__ void __launch_bounds__(256) k_nn(const float* __restrict__ xyz1,
                                            const float* __restrict__ xyz2) {
    __shared__ float4 s2[SPT];
    __shared__ float sd[3][3][128];
    __shared__ int   si[3][3][128];
    const int b = blockIdx.y, tid = threadIdx.x;
    const int q = tid & 63, part = tid >> 6;
    const int n0 = blockIdx.x * 128 + q;      // query A
    const int n1 = n0 + 64;                   // query B
    for (int i = tid; i < SPT; i += 256) {
        const float x = xyz2[(size_t)b * 3072 + i];
        const float y = xyz2[(size_t)b * 3072 + 1024 + i];
        const float z = xyz2[(size_t)b * 3072 + 2048 + i];
        s2[i] = make_float4(x, y, z, fmaf(x, x, fmaf(y, y, z * z)));
    }
    __syncthreads();

    const float pxA = xyz1[((size_t)b * 3 + 0) * NPT + n0];
    const float pyA = xyz1[((size_t)b * 3 + 1) * NPT + n0];
    const float pzA = xyz1[((size_t)b * 3 + 2) * NPT + n0];
    const float pxB = xyz1[((size_t)b * 3 + 0) * NPT + n1];
    const float pyB = xyz1[((size_t)b * 3 + 1) * NPT + n1];
    const float pzB = xyz1[((size_t)b * 3 + 2) * NPT + n1];
    const float mxA = -2.f * pxA, myA = -2.f * pyA, mzA = -2.f * pzA;
    const float mxB = -2.f * pxB, myB = -2.f * pyB, mzB = -2.f * pzB;
    const float a2A = fmaf(pxA, pxA, fmaf(pyA, pyA, pzA * pzA));
    const float a2B = fmaf(pxB, pxB, fmaf(pyB, pyB, pzB * pzB));

    float dA0 = 1e30f, dA1 = 1e30f, dA2 = 1e30f;
    int   iA0 = 0, iA1 = 0, iA2 = 0;
    float dB0 = 1e30f, dB1 = 1e30f, dB2 = 1e30f;
    int   iB0 = 0, iB1 = 0, iB2 = 0;
    const int sbeg = part << 8;
#pragma unroll 2
    for (int s = sbeg; s < sbeg + 256; s++) {
        const float4 v = s2[s];
        const float dA = fmaf(mxA, v.x, fmaf(myA, v.y, fmaf(mzA, v.z, v.w)));
        const float dB = fmaf(mxB, v.x, fmaf(myB, v.y, fmaf(mzB, v.z, v.w)));
        if (dA < dA2) {
            const bool p0 = dA < dA0, p1 = dA < dA1;
            iA2 = p1 ? iA1 : s;
            dA2 = p1 ? dA1 : dA;
            iA1 = p0 ? iA0 : (p1 ? s : iA1);
            dA1 = p0 ? dA0 : (p1 ? dA : dA1);
            iA0 = p0 ? s : iA0;
            dA0 = p0 ? dA : dA0;
        }
        if (dB < dB2) {
            const bool p0 = dB < dB0, p1 = dB < dB1;
            iB2 = p1 ? iB1 : s;
            dB2 = p1 ? dB1 : dB;
            iB1 = p0 ? iB0 : (p1 ? s : iB1);
            dB1 = p0 ? dB0 : (p1 ? dB : dB1);
            iB0 = p0 ? s : iB0;
            dB0 = p0 ? dB : dB0;
        }
    }
    if (part) {
        sd[part - 1][0][q] = dA0; sd[part - 1][1][q] = dA1; sd[part - 1][2][q] = dA2;
        si[part - 1][0][q] = iA0; si[part - 1][1][q] = iA1; si[part - 1][2][q] = iA2;
        sd[part - 1][0][q + 64] = dB0; sd[part - 1][1][q + 64] = dB1; sd[part - 1][2][q + 64] = dB2;
        si[part - 1][0][q + 64] = iB0; si[part - 1][1][q + 64] = iB1; si[part - 1][2][q + 64] = iB2;
    }
    __syncthreads();
    if (part == 0) {
#pragma unroll
        for (int which = 0; which < 2; which++) {
            const int qq = q + which * 64;
            float d0 = which ? dB0 : dA0, d1 = which ? dB1 : dA1, d2 = which ? dB2 : dA2;
            int   i0 = which ? iB0 : iA0, i1 = which ? iB1 : iA1, i2 = which ? iB2 : iA2;
            const float a2 = which ? a2B : a2A;
#pragma unroll
            for (int p = 0; p < 3; p++) {
                float e0 = sd[p][0][qq], e1 = sd[p][1][qq], e2 = sd[p][2][qq];
                int   j0 = si[p][0][qq], j1 = si[p][1][qq], j2 = si[p][2][qq];
                float m0, m1, m2; int o0, o1, o2;
                bool t = e0 < d0;               // ties -> accumulated (lower idx)
                m0 = t ? e0 : d0; o0 = t ? j0 : i0;
                if (t) { e0 = e1; j0 = j1; e1 = e2; j1 = j2; }
                else   { d0 = d1; i0 = i1; d1 = d2; i1 = i2; }
                t = e0 < d0;
                m1 = t ? e0 : d0; o1 = t ? j0 : i0;
                if (t) { e0 = e1; j0 = j1; }
                else   { d0 = d1; i0 = i1; }
                t = e0 < d0;
                m2 = t ? e0 : d0; o2 = t ? j0 : i0;
                d0 = m0; d1 = m1; d2 = m2; i0 = o0; i1 = o1; i2 = o2;
            }
            const float f0 = sqrtf(fmaxf(d0 + a2, 0.f));
            const float f1 = sqrtf(fmaxf(d1 + a2, 0.f));
            const float f2 = sqrtf(fmaxf(d2 + a2, 0.f));
            float w0 = 1.f / (f0 + 1e-10f);
            float w1 = 1.f / (f1 + 1e-10f);
            float w2 = 1.f / (f2 + 1e-10f);
            const float inv = 1.f / (w0 + w1 + w2);
            const int g = b * NPT + blockIdx.x * 128 + qq;
            g_nnw4[g] = make_float4(w0 * inv, w1 * inv, w2 * inv, 0.f);
            g_nni4[g] = make_int4(i0, i1, i2, 0);
        }
    }
}

// ---------------------------------------------------------------------------
// k_gather: warp per query; register accumulation; bf16 hi/lo out.
// ---------------------------------------------------------------------------
__global__ void __launch_bounds__(256) k_gather() {
    const int wid = threadIdx.x >> 5, lane = threadIdx.x & 31;
    const int n = blockIdx.x * 8 + wid;
    const int b = n >> 12;
    const float4 wv = g_nnw4[n];
    const int4   iv = g_nni4[n];
    const float* p2t = g_p2t + (size_t)b * SPT * D2_;
    const float4 v0 = *(const float4*)(p2t + (size_t)iv.x * D2_ + lane * 4);
    const float4 v1 = *(const float4*)(p2t + (size_t)iv.y * D2_ + lane * 4);
    const float4 v2 = *(const float4*)(p2t + (size_t)iv.z * D2_ + lane * 4);
    float4 a;
    a.x = fmaf(wv.x, v0.x, fmaf(wv.y, v1.x, wv.z * v2.x));
    a.y = fmaf(wv.x, v0.y, fmaf(wv.y, v1.y, wv.z * v2.y));
    a.z = fmaf(wv.x, v0.z, fmaf(wv.y, v1.z, wv.z * v2.z));
    a.w = fmaf(wv.x, v0.w, fmaf(wv.y, v1.w, wv.z * v2.w));
    uint32_t h0, l0, h1, l1, h2, l2, h3, l3;
    split_bf16(a.x, h0, l0); split_bf16(a.y, h1, l1);
    split_bf16(a.z, h2, l2); split_bf16(a.w, h3, l3);
    const size_t o = (size_t)n * CIN + D1_ + lane * 4;
    *(uint2*)(g_x1h + o) = make_uint2(h0 | (h1 << 16), h2 | (h3 << 16));
    *(uint2*)(g_x1l + o) = make_uint2(l0 | (l1 << 16), l2 | (l3 << 16));
}

// ---------------------------------------------------------------------------
// Warp-MMA GEMM, FULL-N CTA: C[n,256] = X[n,K] * W[256,K]^T.
// CTA tile 128(M) x 256(N), 512 threads (warps 4Mx4N), K-chunk 64,
// cp.async double buffer. X read from DRAM exactly once per GEMM.
// smem/buffer: Xh 16K | Xl 16K | Wh 32K | Wl 32K = 96KB; x2 = 192KB.
// ---------------------------------------------------------------------------
#define BUFSZ 98304
#define MMA_SMEM (2 * BUFSZ + 1024)

template <int LAYER>
__global__ void __launch_bounds__(512) k_mma() {
    constexpr int K  = (LAYER == 1) ? CIN : CO;
    constexpr int KT = K / 64;
    const __nv_bfloat16* xh = (LAYER == 1) ? g_x1h : g_x2h;
    const __nv_bfloat16* xl = (LAYER == 1) ? g_x1l : g_x2l;
    const __nv_bfloat16* wh = (LAYER == 1) ? g_w1h : g_w2h;
    const __nv_bfloat16* wl = (LAYER == 1) ? g_w1l : g_w2l;
    float* C = g_y1;

    extern __shared__ uint8_t dsm[];
    const uint32_t sbase = (smem_u32(dsm) + 1023) & ~1023u;

    const int tid  = threadIdx.x, wid = tid >> 5, lane = tid & 31;
    const int m0   = blockIdx.x << 7;
    const int wm   = wid & 3, wn = wid >> 2;    // 4(M) x 4(N)

    auto stage = [&](int kt) {
        const uint32_t base = sbase + (kt & 1) * BUFSZ;
        const int k0 = kt * 64;
        // X h+l: 2048 x 16B
#pragma unroll
        for (int i = 0; i < 4; i++) {
            const int q = tid + i * 512;
            const int sel = q >> 10;              // 0 xh, 1 xl
            const int r = (q & 1023) >> 3, c = q & 7;
            const __nv_bfloat16* src = ((sel == 0) ? xh : xl) + (size_t)(m0 + r) * K + k0 + c * 8;
            const uint32_t dst = base + sel * 16384 + r * 128 + (((uint32_t)(c ^ (r & 7))) << 4);
            asm volatile("cp.async.cg.shared.global [%0], [%1], 16;" :: "r"(dst), "l"(src));
        }
        // W h+l: 4096 x 16B (256 rows)
#pragma unroll
        for (int i = 0; i < 8; i++) {
            const int q = tid + i * 512;
            const int sel = q >> 11;              // 0 wh, 1 wl
            const int r = (q & 2047) >> 3, c = q & 7;
            const __nv_bfloat16* src = ((sel == 0) ? wh : wl) + (size_t)r * K + k0 + c * 8;
            const uint32_t dst = base + 32768 + sel * 32768 + r * 128 + (((uint32_t)(c ^ (r & 7))) << 4);
            asm volatile("cp.async.cg.shared.global [%0], [%1], 16;" :: "r"(dst), "l"(src));
        }
        asm volatile("cp.async.commit_group;");
    };

    int rA[2], cAx = lane >> 4;
#pragma unroll
    for (int s = 0; s < 2; s++)
        rA[s] = wm * 32 + s * 16 + (lane & 7) + ((lane >> 3) & 1) * 8;
    int rB[4], cBx = (lane >> 3) & 1;
#pragma unroll
    for (int jj = 0; jj < 4; jj++)
        rB[jj] = wn * 64 + (jj * 2 + (lane >> 4)) * 8 + (lane & 7);

    float acc[2][8][4];
#pragma unroll
    for (int s = 0; s < 2; s++)
#pragma unroll
        for (int j = 0; j < 8; j++)
#pragma unroll
            for (int v = 0; v < 4; v++) acc[s][j][v] = 0.f;

    stage(0);
#pragma unroll 1
    for (int kt = 0; kt < KT; kt++) {
        if (kt + 1 < KT) { stage(kt + 1); asm volatile("cp.async.wait_group 1;"); }
        else             { asm volatile("cp.async.wait_group 0;"); }
        __syncthreads();
        const uint32_t base = sbase + (kt & 1) * BUFSZ;
        const uint32_t bXh = base, bXl = base + 16384, bWh = base + 32768, bWl = base + 65536;
#pragma unroll
        for (int ks = 0; ks < 4; ks++) {
            uint32_t ah[2][4], al[2][4], bh[4][4], bl[4][4];
#pragma unroll
            for (int s = 0; s < 2; s++) {
                const uint32_t off = rA[s] * 128 + (((uint32_t)((ks * 2 + cAx) ^ (rA[s] & 7))) << 4);
                asm volatile("ldmatrix.sync.aligned.m8n8.x4.shared.b16 {%0,%1,%2,%3}, [%4];"
                    : "=r"(ah[s][0]), "=r"(ah[s][1]), "=r"(ah[s][2]), "=r"(ah[s][3]) : "r"(bXh + off));
                asm volatile("ldmatrix.sync.aligned.m8n8.x4.shared.b16 {%0,%1,%2,%3}, [%4];"
                    : "=r"(al[s][0]), "=r"(al[s][1]), "=r"(al[s][2]), "=r"(al[s][3]) : "r"(bXl + off));
            }
#pragma unroll
            for (int jj = 0; jj < 4; jj++) {
                const uint32_t off = rB[jj] * 128 + (((uint32_t)((ks * 2 + cBx) ^ (rB[jj] & 7))) << 4);
                asm volatile("ldmatrix.sync.aligned.m8n8.x4.shared.b16 {%0,%1,%2,%3}, [%4];"
                    : "=r"(bh[jj][0]), "=r"(bh[jj][1]), "=r"(bh[jj][2]), "=r"(bh[jj][3]) : "r"(bWh + off));
                asm volatile("ldmatrix.sync.aligned.m8n8.x4.shared.b16 {%0,%1,%2,%3}, [%4];"
                    : "=r"(bl[jj][0]), "=r"(bl[jj][1]), "=r"(bl[jj][2]), "=r"(bl[jj][3]) : "r"(bWl + off));
            }
#pragma unroll
            for (int s = 0; s < 2; s++)
#pragma unroll
                for (int j = 0; j < 8; j++) {
                    float* cc = acc[s][j];
                    const uint32_t* fh = &bh[j >> 1][(j & 1) * 2];
                    const uint32_t* fl = &bl[j >> 1][(j & 1) * 2];
#define MMA_(A, Bf) asm volatile( \
    "mma.sync.aligned.m16n8k16.row.col.f32.bf16.bf16.f32 " \
    "{%0,%1,%2,%3}, {%4,%5,%6,%7}, {%8,%9}, {%0,%1,%2,%3};" \
    : "+f"(cc[0]), "+f"(cc[1]), "+f"(cc[2]), "+f"(cc[3]) \
    : "r"((A)[0]), "r"((A)[1]), "r"((A)[2]), "r"((A)[3]), "r"((Bf)[0]), "r"((Bf)[1]))
                    MMA_(ah[s], fh);
                    MMA_(al[s], fh);
                    MMA_(ah[s], fl);
#undef MMA_
                }
        }
        __syncthreads();
    }

    // ---- lean epilogue: direct fp32 stores to C[n,256] ----
#pragma unroll
    for (int s = 0; s < 2; s++) {
        const int m = m0 + wm * 32 + s * 16 + (lane >> 2);
#pragma unroll
        for (int j = 0; j < 8; j++) {
            const int n = wn * 64 + j * 8 + (lane & 3) * 2;
            *(float2*)(C + (size_t)m * CO + n)       = make_float2(acc[s][j][0], acc[s][j][1]);
            *(float2*)(C + (size_t)(m + 8) * CO + n) = make_float2(acc[s][j][2], acc[s][j][3]);
        }
    }
}

// ---------------------------------------------------------------------------
// k_stats: per-channel partials over y [n,256]; deterministic.
// ---------------------------------------------------------------------------
__global__ void __launch_bounds__(256) k_stats() {
    __shared__ float4 ss[256], qq[256];
    const int j = blockIdx.x, t = threadIdx.x;
    const int cq = t & 63, rq = t >> 6;
    const float4* y = (const float4*)g_y1;
    float4 s = make_float4(0, 0, 0, 0), q = make_float4(0, 0, 0, 0);
    for (int i = 0; i < 64; i++) {
        const int row = j * 256 + rq * 64 + i;
        const float4 v = y[(size_t)row * 64 + cq];
        s.x += v.x; s.y += v.y; s.z += v.z; s.w += v.w;
        q.x = fmaf(v.x, v.x, q.x); q.y = fmaf(v.y, v.y, q.y);
        q.z = fmaf(v.z, v.z, q.z); q.w = fmaf(v.w, v.w, q.w);
    }
    ss[t] = s; qq[t] = q;
    __syncthreads();
    if (t < 64) {
        float4 a = ss[t], b = ss[t + 64], c = ss[t + 128], d = ss[t + 192];
        float4 e = qq[t], f = qq[t + 64], g = qq[t + 128], h = qq[t + 192];
        float4 so = make_float4((a.x + b.x) + (c.x + d.x), (a.y + b.y) + (c.y + d.y),
                                (a.z + b.z) + (c.z + d.z), (a.w + b.w) + (c.w + d.w));
        float4 qo = make_float4((e.x + f.x) + (g.x + h.x), (e.y + f.y) + (g.y + h.y),
                                (e.z + f.z) + (g.z + h.z), (e.w + f.w) + (g.w + h.w));
        *(float4*)&g_psum[j * 256 + t * 4] = so;
        *(float4*)&g_psq[j * 256 + t * 4]  = qo;
    }
}

// ---------------------------------------------------------------------------
// fold: reduce 256 partials/channel -> folded BN affine
// ---------------------------------------------------------------------------
__global__ void k_fold(const float* __restrict__ gamma, const float* __restrict__ beta,
                       int layer) {
    const int c = threadIdx.x;
    float s = 0.f, q = 0.f;
    for (int j = 0; j < 256; j++) {
        s += g_psum[j * 256 + c];
        q += g_psq[j * 256 + c];
    }
    const float mean = s * (1.f / (float)NS);
    const float var  = q * (1.f / (float)NS) - mean * mean;
    const float a = gamma[c] * rsqrtf(var + 1e-5f);
    const float b = beta[c] - mean * a;
    if (layer == 1) { g_a1[c] = a; g_b1[c] = b; }
    else            { g_a2[c] = a; g_b2[c] = b; }
}

// ---------------------------------------------------------------------------
// x2 = split(relu(a1*y1 + b1))
// ---------------------------------------------------------------------------
__global__ void __launch_bounds__(256) k_x2() {
    const size_t i = (size_t)blockIdx.x * 256 + threadIdx.x;
    const size_t row = i >> 6;
    const int cq = (int)(i & 63), c0 = cq * 4;
    float4 v = ((const float4*)g_y1)[row * 64 + cq];
    const float4 a = *(const float4*)&g_a1[c0];
    const float4 b = *(const float4*)&g_b1[c0];
    v.x = fmaxf(fmaf(a.x, v.x, b.x), 0.f);
    v.y = fmaxf(fmaf(a.y, v.y, b.y), 0.f);
    v.z = fmaxf(fmaf(a.z, v.z, b.z), 0.f);
    v.w = fmaxf(fmaf(a.w, v.w, b.w), 0.f);
    uint32_t h0, l0, h1, l1, h2, l2, h3, l3;
    split_bf16(v.x, h0, l0); split_bf16(v.y, h1, l1);
    split_bf16(v.z, h2, l2); split_bf16(v.w, h3, l3);
    const size_t o = row * CO + c0;
    *(uint2*)(g_x2h + o) = make_uint2(h0 | (h1 << 16), h2 | (h3 << 16));
    *(uint2*)(g_x2l + o) = make_uint2(l0 | (l1 << 16), l2 | (l3 << 16));
}

// ---------------------------------------------------------------------------
// finalize: out[b,o,n] = relu(a2*y2[n,o] + b2)
// ---------------------------------------------------------------------------
__global__ void k_finalize(float* __restrict__ out) {
    __shared__ float t[32][33];
    const int b = blockIdx.z, o0 = blockIdx.y * 32, n0 = blockIdx.x * 32;
    const int tx = threadIdx.x, ty = threadIdx.y;
    const float a = g_a2[o0 + tx], bb = g_b2[o0 + tx];
#pragma unroll
    for (int i = 0; i < 4; i++) {
        const int n = n0 + ty + i * 8;
        const float v = g_y1[(size_t)(b * NPT + n) * CO + o0 + tx];
        t[tx][ty + i * 8] = fmaxf(fmaf(a, v, bb), 0.f);
    }
    __syncthreads();
#pragma unroll
    for (int i = 0; i < 4; i++)
        out[((size_t)b * CO + o0 + ty + i * 8) * NPT + n0 + tx] = t[ty + i * 8][tx];
}

// ---------------------------------------------------------------------------
// Launch
// ---------------------------------------------------------------------------
extern "C" void kernel_launch(void* const* d_in, const int* in_sizes, int n_in,
                              void* d_out, int out_size) {
    const float* xyz1    = (const float*)d_in[0];
    const float* xyz2    = (const float*)d_in[1];
    const float* points1 = (const float*)d_in[2];
    const float* points2 = (const float*)d_in[3];
    const float* W1      = (const float*)d_in[4];
    const float* g1      = (const float*)d_in[6];
    const float* be1     = (const float*)d_in[7];
    const float* W2      = (const float*)d_in[8];
    const float* g2      = (const float*)d_in[10];
    const float* be2     = (const float*)d_in[11];
    float* out = (float*)d_out;

    cudaFuncSetAttribute(k_mma<1>, cudaFuncAttributeMaxDynamicSharedMemorySize, MMA_SMEM);
    cudaFuncSetAttribute(k_mma<2>, cudaFuncAttributeMaxDynamicSharedMemorySize, MMA_SMEM);

    k_wsplit<<<640, 256>>>(W1, W2);
    k_tp2<<<dim3(32, 4, 16), dim3(32, 8)>>>(points2);
    k_tp1<<<dim3(128, 8, 16), dim3(32, 8)>>>(points1);
    k_nn<<<dim3(32, 16), 256>>>(xyz1, xyz2);
    k_gather<<<8192, 256>>>();
    k_mma<1><<<512, 512, MMA_SMEM>>>();
    k_stats<<<256, 256>>>();
    k_fold<<<1, 256>>>(g1, be1, 1);
    k_x2<<<16384, 256>>>();
    k_mma<2><<<512, 512, MMA_SMEM>>>();
    k_stats<<<256, 256>>>();
    k_fold<<<1, 256>>>(g2, be2, 2);
    k_finalize<<<dim3(128, 8, 16), dim3(32, 8)>>>(out);
}

// round 12
// speedup vs baseline: 1.0597x; 1.0597x over previous
#include <cuda_runtime.h>
#include <cuda_bf16.h>
#include <cstdint>
#include <cstddef>

#define B_   16
#define NPT  4096
#define SPT  1024
#define D1_  256
#define D2_  128
#define CIN  384
#define CO   256
#define NS   (B_*NPT)   // 65536

// ---------------------------------------------------------------------------
// Scratch
// ---------------------------------------------------------------------------
__device__ float         g_p2t[B_ * SPT * D2_];
__device__ __nv_bfloat16 g_x1h[(size_t)NS * CIN];
__device__ __nv_bfloat16 g_x1l[(size_t)NS * CIN];
__device__ __nv_bfloat16 g_x2h[(size_t)NS * CO];
__device__ __nv_bfloat16 g_x2l[(size_t)NS * CO];
__device__ float         g_y1[(size_t)NS * CO];     // y1, then reused as y2
__device__ __nv_bfloat16 g_w1h[CO * CIN], g_w1l[CO * CIN];
__device__ __nv_bfloat16 g_w2h[CO * CO],  g_w2l[CO * CO];
__device__ float g_psum[256 * 256], g_psq[256 * 256]; // [rowblock][channel] partials
__device__ float g_a1[CO], g_b1[CO], g_a2[CO], g_b2[CO];
__device__ float4 g_nnw4[NS];   // 3 normalized weights per query
__device__ int4   g_nni4[NS];   // 3 neighbor indices per query

__device__ __forceinline__ uint32_t smem_u32(const void* p) {
    uint32_t a;
    asm("{ .reg .u64 t; cvta.to.shared.u64 t, %1; cvt.u32.u64 %0, t; }" : "=r"(a) : "l"(p));
    return a;
}
__device__ __forceinline__ void split_bf16(float a, uint32_t& h, uint32_t& l) {
    __nv_bfloat16 hb = __float2bfloat16(a);
    __nv_bfloat16 lb = __float2bfloat16(a - __bfloat162float(hb));
    h = (uint32_t)__bfloat16_as_ushort(hb);
    l = (uint32_t)__bfloat16_as_ushort(lb);
}

// ---------------------------------------------------------------------------
// k_prep: fused W-split + points2 transpose + points1 transpose/split.
// blockIdx.x ranges:  [0,640)            -> W split (163840 elems)
//                     [640, 640+2048)    -> tp2
//                     [2688, 2688+16384) -> tp1
// ---------------------------------------------------------------------------
__global__ void __launch_bounds__(256) k_prep(const float* __restrict__ W1,
                                              const float* __restrict__ W2,
                                              const float* __restrict__ p2,
                                              const float* __restrict__ p1) {
    __shared__ float t[32][33];
    const int bi = blockIdx.x, tid = threadIdx.x;
    const int tx = tid & 31, ty = tid >> 5;

    if (bi < 640) {                       // ---- W split ----
        const int i = bi * 256 + tid;
        uint32_t h, l;
        if (i < CO * CIN) {
            split_bf16(W1[i], h, l);
            g_w1h[i] = __ushort_as_bfloat16((unsigned short)h);
            g_w1l[i] = __ushort_as_bfloat16((unsigned short)l);
        } else {
            const int j = i - CO * CIN;
            split_bf16(W2[j], h, l);
            g_w2h[j] = __ushort_as_bfloat16((unsigned short)h);
            g_w2l[j] = __ushort_as_bfloat16((unsigned short)l);
        }
        return;
    }
    if (bi < 2688) {                      // ---- tp2: [B,D2,S] -> [B,S,D2] ----
        const int idx = bi - 640;
        const int b = idx >> 7, rem = idx & 127;
        const int c0 = (rem >> 5) * 32, s0 = (rem & 31) * 32;
#pragma unroll
        for (int i = 0; i < 4; i++)
            t[ty + i * 8][tx] = p2[((size_t)b * D2_ + c0 + ty + i * 8) * SPT + s0 + tx];
        __syncthreads();
#pragma unroll
        for (int i = 0; i < 4; i++)
            g_p2t[((size_t)b * SPT + s0 + ty + i * 8) * D2_ + c0 + tx] = t[tx][ty + i * 8];
        return;
    }
    {                                     // ---- tp1: X1 cols [0,256) ----
        const int idx = bi - 2688;
        const int b = idx >> 10, rem = idx & 1023;
        const int c0 = (rem >> 7) * 32, n0 = (rem & 127) * 32;
#pragma unroll
        for (int i = 0; i < 4; i++)
            t[ty + i * 8][tx] = p1[((size_t)b * D1_ + c0 + ty + i * 8) * NPT + n0 + tx];
        __syncthreads();
#pragma unroll
        for (int w = 0; w < 2; w++) {
            const int v = w * 256 + tid;
            const int n = v >> 4, u = v & 15;
            uint32_t h0, l0, h1, l1;
            split_bf16(t[2 * u][n], h0, l0);
            split_bf16(t[2 * u + 1][n], h1, l1);
            const size_t a = (size_t)(b * NPT + n0 + n) * CIN + c0 + 2 * u;
            *(uint32_t*)(g_x1h + a) = h0 | (h1 << 16);
            *(uint32_t*)(g_x1l + a) = l0 | (l1 << 16);
        }
    }
}

// ---------------------------------------------------------------------------
// k_nn: split-S 3-NN (R9 config: 2 threads/query, 512 refs each, rare-branch
// insertion, smem merge of the two sorted triples).
// ---------------------------------------------------------------------------
__global__ void __launch_bounds__(256) k_nn(const float* __restrict__ xyz1,
                                            const float* __restrict__ xyz2) {
    __shared__ float4 s2[SPT];
    __shared__ float sd[3][128];
    __shared__ int   si[3][128];
    const int b = blockIdx.y, tid = threadIdx.x;
    const int q = tid & 127, half = tid >> 7;
    const int n = blockIdx.x * 128 + q;
    for (int i = tid; i < SPT; i += 256) {
        const float x = xyz2[(size_t)b * 3072 + i];
        const float y = xyz2[(size_t)b * 3072 + 1024 + i];
        const float z = xyz2[(size_t)b * 3072 + 2048 + i];
        s2[i] = make_float4(x, y, z, fmaf(x, x, fmaf(y, y, z * z)));
    }
    __syncthreads();

    const float px = xyz1[((size_t)b * 3 + 0) * NPT + n];
    const float py = xyz1[((size_t)b * 3 + 1) * NPT + n];
    const float pz = xyz1[((size_t)b * 3 + 2) * NPT + n];
    const float mx = -2.f * px, my = -2.f * py, mz = -2.f * pz;
    const float a2 = fmaf(px, px, fmaf(py, py, pz * pz));

    float d0 = 1e30f, d1 = 1e30f, d2 = 1e30f;
    int   i0 = 0, i1 = 0, i2 = 0;
    const int sbeg = half << 9;
#pragma unroll 4
    for (int s = sbeg; s < sbeg + 512; s++) {
        const float4 v = s2[s];
        const float d = fmaf(mx, v.x, fmaf(my, v.y, fmaf(mz, v.z, v.w)));
        if (d < d2) {
            const bool p0 = d < d0, p1 = d < d1;
            i2 = p1 ? i1 : s;
            d2 = p1 ? d1 : d;
            i1 = p0 ? i0 : (p1 ? s : i1);
            d1 = p0 ? d0 : (p1 ? d : d1);
            i0 = p0 ? s : i0;
            d0 = p0 ? d : d0;
        }
    }
    if (half) {
        sd[0][q] = d0; sd[1][q] = d1; sd[2][q] = d2;
        si[0][q] = i0; si[1][q] = i1; si[2][q] = i2;
    }
    __syncthreads();
    if (!half) {
        float b0 = sd[0][q], b1 = sd[1][q], b2 = sd[2][q];
        int   j0 = si[0][q], j1 = si[1][q], j2 = si[2][q];
        float m0, m1, m2; int o0, o1, o2;
        bool t = b0 < d0;                       // ties -> lower-index half (d)
        m0 = t ? b0 : d0; o0 = t ? j0 : i0;
        if (t) { b0 = b1; j0 = j1; b1 = b2; j1 = j2; }
        else   { d0 = d1; i0 = i1; d1 = d2; i1 = i2; }
        t = b0 < d0;
        m1 = t ? b0 : d0; o1 = t ? j0 : i0;
        if (t) { b0 = b1; j0 = j1; }
        else   { d0 = d1; i0 = i1; }
        t = b0 < d0;
        m2 = t ? b0 : d0; o2 = t ? j0 : i0;

        const float f0 = sqrtf(fmaxf(m0 + a2, 0.f));
        const float f1 = sqrtf(fmaxf(m1 + a2, 0.f));
        const float f2 = sqrtf(fmaxf(m2 + a2, 0.f));
        float w0 = 1.f / (f0 + 1e-10f);
        float w1 = 1.f / (f1 + 1e-10f);
        float w2 = 1.f / (f2 + 1e-10f);
        const float inv = 1.f / (w0 + w1 + w2);
        const int g = b * NPT + n;
        g_nnw4[g] = make_float4(w0 * inv, w1 * inv, w2 * inv, 0.f);
        g_nni4[g] = make_int4(o0, o1, o2, 0);
    }
}

// ---------------------------------------------------------------------------
// k_gather: warp per query; register accumulation; bf16 hi/lo out.
// ---------------------------------------------------------------------------
__global__ void __launch_bounds__(256) k_gather() {
    const int wid = threadIdx.x >> 5, lane = threadIdx.x & 31;
    const int n = blockIdx.x * 8 + wid;
    const int b = n >> 12;
    const float4 wv = g_nnw4[n];
    const int4   iv = g_nni4[n];
    const float* p2t = g_p2t + (size_t)b * SPT * D2_;
    const float4 v0 = *(const float4*)(p2t + (size_t)iv.x * D2_ + lane * 4);
    const float4 v1 = *(const float4*)(p2t + (size_t)iv.y * D2_ + lane * 4);
    const float4 v2 = *(const float4*)(p2t + (size_t)iv.z * D2_ + lane * 4);
    float4 a;
    a.x = fmaf(wv.x, v0.x, fmaf(wv.y, v1.x, wv.z * v2.x));
    a.y = fmaf(wv.x, v0.y, fmaf(wv.y, v1.y, wv.z * v2.y));
    a.z = fmaf(wv.x, v0.z, fmaf(wv.y, v1.z, wv.z * v2.z));
    a.w = fmaf(wv.x, v0.w, fmaf(wv.y, v1.w, wv.z * v2.w));
    uint32_t h0, l0, h1, l1, h2, l2, h3, l3;
    split_bf16(a.x, h0, l0); split_bf16(a.y, h1, l1);
    split_bf16(a.z, h2, l2); split_bf16(a.w, h3, l3);
    const size_t o = (size_t)n * CIN + D1_ + lane * 4;
    *(uint2*)(g_x1h + o) = make_uint2(h0 | (h1 << 16), h2 | (h3 << 16));
    *(uint2*)(g_x1l + o) = make_uint2(l0 | (l1 << 16), l2 | (l3 << 16));
}

// ---------------------------------------------------------------------------
// Warp-MMA GEMM (R9 config: CTA 128x128, 256 threads, grid (2,512) for X L2
// pairing, K-chunk 64, cp.async double buffer, 8 warps 4Mx2N).
// NEW: term-major MMA ordering — each sweep issues 16 MMAs into 16 distinct
// accumulator quads, eliminating back-to-back accumulator RAW chains.
// ---------------------------------------------------------------------------
#define MMA_SMEM (2 * 65536 + 1024)

template <int LAYER>
__global__ void __launch_bounds__(256) k_mma() {
    constexpr int K  = (LAYER == 1) ? CIN : CO;
    constexpr int KT = K / 64;
    const __nv_bfloat16* xh = (LAYER == 1) ? g_x1h : g_x2h;
    const __nv_bfloat16* xl = (LAYER == 1) ? g_x1l : g_x2l;
    const __nv_bfloat16* wh = (LAYER == 1) ? g_w1h : g_w2h;
    const __nv_bfloat16* wl = (LAYER == 1) ? g_w1l : g_w2l;
    float* C = g_y1;

    extern __shared__ uint8_t dsm[];
    const uint32_t sbase = (smem_u32(dsm) + 1023) & ~1023u;

    const int tid  = threadIdx.x, wid = tid >> 5, lane = tid & 31;
    const int m0   = blockIdx.y << 7;     // sample tile (slow axis)
    const int n0   = blockIdx.x << 7;     // channel tile (fast axis, pair shares X)
    const int wm   = wid & 3, wn = wid >> 2;

    auto stage = [&](int kt) {
        const int buf = kt & 1;
        const uint32_t base = sbase + buf * 65536;
        const int k0 = kt * 64;
#pragma unroll
        for (int i = 0; i < 16; i++) {
            const int q = tid + i * 256;
            const int sel = q >> 10;
            const int r = (q & 1023) >> 3, c = q & 7;
            const __nv_bfloat16* src;
            if      (sel == 0) src = xh + (size_t)(m0 + r) * K + k0 + c * 8;
            else if (sel == 1) src = xl + (size_t)(m0 + r) * K + k0 + c * 8;
            else if (sel == 2) src = wh + (size_t)(n0 + r) * K + k0 + c * 8;
            else               src = wl + (size_t)(n0 + r) * K + k0 + c * 8;
            const uint32_t dst = base + sel * 16384 + r * 128 + (((uint32_t)(c ^ (r & 7))) << 4);
            asm volatile("cp.async.cg.shared.global [%0], [%1], 16;" :: "r"(dst), "l"(src));
        }
        asm volatile("cp.async.commit_group;");
    };

    int rA[2], cAx = lane >> 4;
#pragma unroll
    for (int s = 0; s < 2; s++)
        rA[s] = wm * 32 + s * 16 + (lane & 7) + ((lane >> 3) & 1) * 8;
    int rB[4], cBx = (lane >> 3) & 1;
#pragma unroll
    for (int jj = 0; jj < 4; jj++)
        rB[jj] = wn * 64 + (jj * 2 + (lane >> 4)) * 8 + (lane & 7);

    float acc[2][8][4];
#pragma unroll
    for (int s = 0; s < 2; s++)
#pragma unroll
        for (int j = 0; j < 8; j++)
#pragma unroll
            for (int v = 0; v < 4; v++) acc[s][j][v] = 0.f;

    stage(0);
#pragma unroll 1
    for (int kt = 0; kt < KT; kt++) {
        if (kt + 1 < KT) { stage(kt + 1); asm volatile("cp.async.wait_group 1;"); }
        else             { asm volatile("cp.async.wait_group 0;"); }
        __syncthreads();
        const uint32_t base = sbase + (kt & 1) * 65536;
        const uint32_t bXh = base, bXl = base + 16384, bWh = base + 32768, bWl = base + 49152;
#pragma unroll
        for (int ks = 0; ks < 4; ks++) {
            uint32_t ah[2][4], al[2][4], bh[4][4], bl[4][4];
#pragma unroll
            for (int s = 0; s < 2; s++) {
                const uint32_t off = rA[s] * 128 + (((uint32_t)((ks * 2 + cAx) ^ (rA[s] & 7))) << 4);
                asm volatile("ldmatrix.sync.aligned.m8n8.x4.shared.b16 {%0,%1,%2,%3}, [%4];"
                    : "=r"(ah[s][0]), "=r"(ah[s][1]), "=r"(ah[s][2]), "=r"(ah[s][3]) : "r"(bXh + off));
                asm volatile("ldmatrix.sync.aligned.m8n8.x4.shared.b16 {%0,%1,%2,%3}, [%4];"
                    : "=r"(al[s][0]), "=r"(al[s][1]), "=r"(al[s][2]), "=r"(al[s][3]) : "r"(bXl + off));
            }
#pragma unroll
            for (int jj = 0; jj < 4; jj++) {
                const uint32_t off = rB[jj] * 128 + (((uint32_t)((ks * 2 + cBx) ^ (rB[jj] & 7))) << 4);
                asm volatile("ldmatrix.sync.aligned.m8n8.x4.shared.b16 {%0,%1,%2,%3}, [%4];"
                    : "=r"(bh[jj][0]), "=r"(bh[jj][1]), "=r"(bh[jj][2]), "=r"(bh[jj][3]) : "r"(bWh + off));
                asm volatile("ldmatrix.sync.aligned.m8n8.x4.shared.b16 {%0,%1,%2,%3}, [%4];"
                    : "=r"(bl[jj][0]), "=r"(bl[jj][1]), "=r"(bl[jj][2]), "=r"(bl[jj][3]) : "r"(bWl + off));
            }
#define MMA_(A, Bf, CC) asm volatile( \
    "mma.sync.aligned.m16n8k16.row.col.f32.bf16.bf16.f32 " \
    "{%0,%1,%2,%3}, {%4,%5,%6,%7}, {%8,%9}, {%0,%1,%2,%3};" \
    : "+f"((CC)[0]), "+f"((CC)[1]), "+f"((CC)[2]), "+f"((CC)[3]) \
    : "r"((A)[0]), "r"((A)[1]), "r"((A)[2]), "r"((A)[3]), "r"((Bf)[0]), "r"((Bf)[1]))
            // term 1: Xh * Wh  (16 independent accumulators back-to-back)
#pragma unroll
            for (int s = 0; s < 2; s++)
#pragma unroll
                for (int j = 0; j < 8; j++)
                    MMA_(ah[s], (&bh[j >> 1][(j & 1) * 2]), acc[s][j]);
            // term 2: Xl * Wh
#pragma unroll
            for (int s = 0; s < 2; s++)
#pragma unroll
                for (int j = 0; j < 8; j++)
                    MMA_(al[s], (&bh[j >> 1][(j & 1) * 2]), acc[s][j]);
            // term 3: Xh * Wl
#pragma unroll
            for (int s = 0; s < 2; s++)
#pragma unroll
                for (int j = 0; j < 8; j++)
                    MMA_(ah[s], (&bl[j >> 1][(j & 1) * 2]), acc[s][j]);
#undef MMA_
        }
        __syncthreads();
    }

    // ---- lean epilogue: direct fp32 stores to C[n,256] ----
#pragma unroll
    for (int s = 0; s < 2; s++) {
        const int m = m0 + wm * 32 + s * 16 + (lane >> 2);
#pragma unroll
        for (int j = 0; j < 8; j++) {
            const int n = n0 + wn * 64 + j * 8 + (lane & 3) * 2;
            *(float2*)(C + (size_t)m * CO + n)       = make_float2(acc[s][j][0], acc[s][j][1]);
            *(float2*)(C + (size_t)(m + 8) * CO + n) = make_float2(acc[s][j][2], acc[s][j][3]);
        }
    }
}

// ---------------------------------------------------------------------------
// k_stats: per-channel partials over y [n,256]; deterministic.
// ---------------------------------------------------------------------------
__global__ void __launch_bounds__(256) k_stats() {
    __shared__ float4 ss[256], qq[256];
    const int j = blockIdx.x, t = threadIdx.x;
    const int cq = t & 63, rq = t >> 6;
    const float4* y = (const float4*)g_y1;
    float4 s = make_float4(0, 0, 0, 0), q = make_float4(0, 0, 0, 0);
    for (int i = 0; i < 64; i++) {
        const int row = j * 256 + rq * 64 + i;
        const float4 v = y[(size_t)row * 64 + cq];
        s.x += v.x; s.y += v.y; s.z += v.z; s.w += v.w;
        q.x = fmaf(v.x, v.x, q.x); q.y = fmaf(v.y, v.y, q.y);
        q.z = fmaf(v.z, v.z, q.z); q.w = fmaf(v.w, v.w, q.w);
    }
    ss[t] = s; qq[t] = q;
    __syncthreads();
    if (t < 64) {
        float4 a = ss[t], b = ss[t + 64], c = ss[t + 128], d = ss[t + 192];
        float4 e = qq[t], f = qq[t + 64], g = qq[t + 128], h = qq[t + 192];
        float4 so = make_float4((a.x + b.x) + (c.x + d.x), (a.y + b.y) + (c.y + d.y),
                                (a.z + b.z) + (c.z + d.z), (a.w + b.w) + (c.w + d.w));
        float4 qo = make_float4((e.x + f.x) + (g.x + h.x), (e.y + f.y) + (g.y + h.y),
                                (e.z + f.z) + (g.z + h.z), (e.w + f.w) + (g.w + h.w));
        *(float4*)&g_psum[j * 256 + t * 4] = so;
        *(float4*)&g_psq[j * 256 + t * 4]  = qo;
    }
}

// ---------------------------------------------------------------------------
// fold: reduce 256 partials/channel -> folded BN affine
// ---------------------------------------------------------------------------
__global__ void k_fold(const float* __restrict__ gamma, const float* __restrict__ beta,
                       int layer) {
    const int c = threadIdx.x;
    float s = 0.f, q = 0.f;
    for (int j = 0; j < 256; j++) {
        s += g_psum[j * 256 + c];
        q += g_psq[j * 256 + c];
    }
    const float mean = s * (1.f / (float)NS);
    const float var  = q * (1.f / (float)NS) - mean * mean;
    const float a = gamma[c] * rsqrtf(var + 1e-5f);
    const float b = beta[c] - mean * a;
    if (layer == 1) { g_a1[c] = a; g_b1[c] = b; }
    else            { g_a2[c] = a; g_b2[c] = b; }
}

// ---------------------------------------------------------------------------
// x2 = split(relu(a1*y1 + b1))
// ---------------------------------------------------------------------------
__global__ void __launch_bounds__(256) k_x2() {
    const size_t i = (size_t)blockIdx.x * 256 + threadIdx.x;
    const size_t row = i >> 6;
    const int cq = (int)(i & 63), c0 = cq * 4;
    float4 v = ((const float4*)g_y1)[row * 64 + cq];
    const float4 a = *(const float4*)&g_a1[c0];
    const float4 b = *(const float4*)&g_b1[c0];
    v.x = fmaxf(fmaf(a.x, v.x, b.x), 0.f);
    v.y = fmaxf(fmaf(a.y, v.y, b.y), 0.f);
    v.z = fmaxf(fmaf(a.z, v.z, b.z), 0.f);
    v.w = fmaxf(fmaf(a.w, v.w, b.w), 0.f);
    uint32_t h0, l0, h1, l1, h2, l2, h3, l3;
    split_bf16(v.x, h0, l0); split_bf16(v.y, h1, l1);
    split_bf16(v.z, h2, l2); split_bf16(v.w, h3, l3);
    const size_t o = row * CO + c0;
    *(uint2*)(g_x2h + o) = make_uint2(h0 | (h1 << 16), h2 | (h3 << 16));
    *(uint2*)(g_x2l + o) = make_uint2(l0 | (l1 << 16), l2 | (l3 << 16));
}

// ---------------------------------------------------------------------------
// finalize: out[b,o,n] = relu(a2*y2[n,o] + b2)
// ---------------------------------------------------------------------------
__global__ void k_finalize(float* __restrict__ out) {
    __shared__ float t[32][33];
    const int b = blockIdx.z, o0 = blockIdx.y * 32, n0 = blockIdx.x * 32;
    const int tx = threadIdx.x, ty = threadIdx.y;
    const float a = g_a2[o0 + tx], bb = g_b2[o0 + tx];
#pragma unroll
    for (int i = 0; i < 4; i++) {
        const int n = n0 + ty + i * 8;
        const float v = g_y1[(size_t)(b * NPT + n) * CO + o0 + tx];
        t[tx][ty + i * 8] = fmaxf(fmaf(a, v, bb), 0.f);
    }
    __syncthreads();
#pragma unroll
    for (int i = 0; i < 4; i++)
        out[((size_t)b * CO + o0 + ty + i * 8) * NPT + n0 + tx] = t[ty + i * 8][tx];
}

// ---------------------------------------------------------------------------
// Launch
// ---------------------------------------------------------------------------
extern "C" void kernel_launch(void* const* d_in, const int* in_sizes, int n_in,
                              void* d_out, int out_size) {
    const float* xyz1    = (const float*)d_in[0];
    const float* xyz2    = (const float*)d_in[1];
    const float* points1 = (const float*)d_in[2];
    const float* points2 = (const float*)d_in[3];
    const float* W1      = (const float*)d_in[4];
    const float* g1      = (const float*)d_in[6];
    const float* be1     = (const float*)d_in[7];
    const float* W2      = (const float*)d_in[8];
    const float* g2      = (const float*)d_in[10];
    const float* be2     = (const float*)d_in[11];
    float* out = (float*)d_out;

    cudaFuncSetAttribute(k_mma<1>, cudaFuncAttributeMaxDynamicSharedMemorySize, MMA_SMEM);
    cudaFuncSetAttribute(k_mma<2>, cudaFuncAttributeMaxDynamicSharedMemorySize, MMA_SMEM);

    k_prep<<<19072, 256>>>(W1, W2, points2, points1);
    k_nn<<<dim3(32, 16), 256>>>(xyz1, xyz2);
    k_gather<<<8192, 256>>>();
    k_mma<1><<<dim3(2, 512), 256, MMA_SMEM>>>();
    k_stats<<<256, 256>>>();
    k_fold<<<1, 256>>>(g1, be1, 1);
    k_x2<<<16384, 256>>>();
    k_mma<2><<<dim3(2, 512), 256, MMA_SMEM>>>();
    k_stats<<<256, 256>>>();
    k_fold<<<1, 256>>>(g2, be2, 2);
    k_finalize<<<dim3(128, 8, 16), dim3(32, 8)>>>(out);
}

// round 13
// speedup vs baseline: 1.1334x; 1.0695x over previous
#include <cuda_runtime.h>
#include <cuda_bf16.h>
#include <cstdint>
#include <cstddef>

#define B_   16
#define NPT  4096
#define SPT  1024
#define D1_  256
#define D2_  128
#define CIN  384
#define CO   256
#define NS   (B_*NPT)   // 65536

// ---------------------------------------------------------------------------
// Scratch
// ---------------------------------------------------------------------------
__device__ float         g_p2t[B_ * SPT * D2_];
__device__ __nv_bfloat16 g_x1h[(size_t)NS * CIN];
__device__ __nv_bfloat16 g_x1l[(size_t)NS * CIN];
__device__ __nv_bfloat16 g_x2h[(size_t)NS * CO];
__device__ __nv_bfloat16 g_x2l[(size_t)NS * CO];
__device__ float         g_y1[(size_t)NS * CO];     // y1, then reused as y2
__device__ __nv_bfloat16 g_w1h[CO * CIN], g_w1l[CO * CIN];
__device__ __nv_bfloat16 g_w2h[CO * CO],  g_w2l[CO * CO];
__device__ float g_psum[256 * 256], g_psq[256 * 256]; // [rowblock][channel] partials
__device__ float g_a1[CO], g_b1[CO], g_a2[CO], g_b2[CO];
__device__ float4 g_nnw4[NS];   // 3 normalized weights per query
__device__ int4   g_nni4[NS];   // 3 neighbor indices per query

__device__ __forceinline__ uint32_t smem_u32(const void* p) {
    uint32_t a;
    asm("{ .reg .u64 t; cvta.to.shared.u64 t, %1; cvt.u32.u64 %0, t; }" : "=r"(a) : "l"(p));
    return a;
}
__device__ __forceinline__ void split_bf16(float a, uint32_t& h, uint32_t& l) {
    __nv_bfloat16 hb = __float2bfloat16(a);
    __nv_bfloat16 lb = __float2bfloat16(a - __bfloat162float(hb));
    h = (uint32_t)__bfloat16_as_ushort(hb);
    l = (uint32_t)__bfloat16_as_ushort(lb);
}

// ---------------------------------------------------------------------------
// k_prep: fused W-split + points2 transpose + points1 transpose/split.
// ---------------------------------------------------------------------------
__global__ void __launch_bounds__(256) k_prep(const float* __restrict__ W1,
                                              const float* __restrict__ W2,
                                              const float* __restrict__ p2,
                                              const float* __restrict__ p1) {
    __shared__ float t[32][33];
    const int bi = blockIdx.x, tid = threadIdx.x;
    const int tx = tid & 31, ty = tid >> 5;

    if (bi < 640) {                       // ---- W split ----
        const int i = bi * 256 + tid;
        uint32_t h, l;
        if (i < CO * CIN) {
            split_bf16(W1[i], h, l);
            g_w1h[i] = __ushort_as_bfloat16((unsigned short)h);
            g_w1l[i] = __ushort_as_bfloat16((unsigned short)l);
        } else {
            const int j = i - CO * CIN;
            split_bf16(W2[j], h, l);
            g_w2h[j] = __ushort_as_bfloat16((unsigned short)h);
            g_w2l[j] = __ushort_as_bfloat16((unsigned short)l);
        }
        return;
    }
    if (bi < 2688) {                      // ---- tp2: [B,D2,S] -> [B,S,D2] ----
        const int idx = bi - 640;
        const int b = idx >> 7, rem = idx & 127;
        const int c0 = (rem >> 5) * 32, s0 = (rem & 31) * 32;
#pragma unroll
        for (int i = 0; i < 4; i++)
            t[ty + i * 8][tx] = p2[((size_t)b * D2_ + c0 + ty + i * 8) * SPT + s0 + tx];
        __syncthreads();
#pragma unroll
        for (int i = 0; i < 4; i++)
            g_p2t[((size_t)b * SPT + s0 + ty + i * 8) * D2_ + c0 + tx] = t[tx][ty + i * 8];
        return;
    }
    {                                     // ---- tp1: X1 cols [0,256) ----
        const int idx = bi - 2688;
        const int b = idx >> 10, rem = idx & 1023;
        const int c0 = (rem >> 7) * 32, n0 = (rem & 127) * 32;
#pragma unroll
        for (int i = 0; i < 4; i++)
            t[ty + i * 8][tx] = p1[((size_t)b * D1_ + c0 + ty + i * 8) * NPT + n0 + tx];
        __syncthreads();
#pragma unroll
        for (int w = 0; w < 2; w++) {
            const int v = w * 256 + tid;
            const int n = v >> 4, u = v & 15;
            uint32_t h0, l0, h1, l1;
            split_bf16(t[2 * u][n], h0, l0);
            split_bf16(t[2 * u + 1][n], h1, l1);
            const size_t a = (size_t)(b * NPT + n0 + n) * CIN + c0 + 2 * u;
            *(uint32_t*)(g_x1h + a) = h0 | (h1 << 16);
            *(uint32_t*)(g_x1l + a) = l0 | (l1 << 16);
        }
    }
}

// ---------------------------------------------------------------------------
// k_nn: split-S 3-NN (2 threads/query, rare-branch insertion, smem merge).
// ---------------------------------------------------------------------------
__global__ void __launch_bounds__(256) k_nn(const float* __restrict__ xyz1,
                                            const float* __restrict__ xyz2) {
    __shared__ float4 s2[SPT];
    __shared__ float sd[3][128];
    __shared__ int   si[3][128];
    const int b = blockIdx.y, tid = threadIdx.x;
    const int q = tid & 127, half = tid >> 7;
    const int n = blockIdx.x * 128 + q;
    for (int i = tid; i < SPT; i += 256) {
        const float x = xyz2[(size_t)b * 3072 + i];
        const float y = xyz2[(size_t)b * 3072 + 1024 + i];
        const float z = xyz2[(size_t)b * 3072 + 2048 + i];
        s2[i] = make_float4(x, y, z, fmaf(x, x, fmaf(y, y, z * z)));
    }
    __syncthreads();

    const float px = xyz1[((size_t)b * 3 + 0) * NPT + n];
    const float py = xyz1[((size_t)b * 3 + 1) * NPT + n];
    const float pz = xyz1[((size_t)b * 3 + 2) * NPT + n];
    const float mx = -2.f * px, my = -2.f * py, mz = -2.f * pz;
    const float a2 = fmaf(px, px, fmaf(py, py, pz * pz));

    float d0 = 1e30f, d1 = 1e30f, d2 = 1e30f;
    int   i0 = 0, i1 = 0, i2 = 0;
    const int sbeg = half << 9;
#pragma unroll 4
    for (int s = sbeg; s < sbeg + 512; s++) {
        const float4 v = s2[s];
        const float d = fmaf(mx, v.x, fmaf(my, v.y, fmaf(mz, v.z, v.w)));
        if (d < d2) {
            const bool p0 = d < d0, p1 = d < d1;
            i2 = p1 ? i1 : s;
            d2 = p1 ? d1 : d;
            i1 = p0 ? i0 : (p1 ? s : i1);
            d1 = p0 ? d0 : (p1 ? d : d1);
            i0 = p0 ? s : i0;
            d0 = p0 ? d : d0;
        }
    }
    if (half) {
        sd[0][q] = d0; sd[1][q] = d1; sd[2][q] = d2;
        si[0][q] = i0; si[1][q] = i1; si[2][q] = i2;
    }
    __syncthreads();
    if (!half) {
        float b0 = sd[0][q], b1 = sd[1][q], b2 = sd[2][q];
        int   j0 = si[0][q], j1 = si[1][q], j2 = si[2][q];
        float m0, m1, m2; int o0, o1, o2;
        bool t = b0 < d0;                       // ties -> lower-index half (d)
        m0 = t ? b0 : d0; o0 = t ? j0 : i0;
        if (t) { b0 = b1; j0 = j1; b1 = b2; j1 = j2; }
        else   { d0 = d1; i0 = i1; d1 = d2; i1 = i2; }
        t = b0 < d0;
        m1 = t ? b0 : d0; o1 = t ? j0 : i0;
        if (t) { b0 = b1; j0 = j1; }
        else   { d0 = d1; i0 = i1; }
        t = b0 < d0;
        m2 = t ? b0 : d0; o2 = t ? j0 : i0;

        const float f0 = sqrtf(fmaxf(m0 + a2, 0.f));
        const float f1 = sqrtf(fmaxf(m1 + a2, 0.f));
        const float f2 = sqrtf(fmaxf(m2 + a2, 0.f));
        float w0 = 1.f / (f0 + 1e-10f);
        float w1 = 1.f / (f1 + 1e-10f);
        float w2 = 1.f / (f2 + 1e-10f);
        const float inv = 1.f / (w0 + w1 + w2);
        const int g = b * NPT + n;
        g_nnw4[g] = make_float4(w0 * inv, w1 * inv, w2 * inv, 0.f);
        g_nni4[g] = make_int4(o0, o1, o2, 0);
    }
}

// ---------------------------------------------------------------------------
// k_gather: warp per query; register accumulation; bf16 hi/lo out.
// ---------------------------------------------------------------------------
__global__ void __launch_bounds__(256) k_gather() {
    const int wid = threadIdx.x >> 5, lane = threadIdx.x & 31;
    const int n = blockIdx.x * 8 + wid;
    const int b = n >> 12;
    const float4 wv = g_nnw4[n];
    const int4   iv = g_nni4[n];
    const float* p2t = g_p2t + (size_t)b * SPT * D2_;
    const float4 v0 = *(const float4*)(p2t + (size_t)iv.x * D2_ + lane * 4);
    const float4 v1 = *(const float4*)(p2t + (size_t)iv.y * D2_ + lane * 4);
    const float4 v2 = *(const float4*)(p2t + (size_t)iv.z * D2_ + lane * 4);
    float4 a;
    a.x = fmaf(wv.x, v0.x, fmaf(wv.y, v1.x, wv.z * v2.x));
    a.y = fmaf(wv.x, v0.y, fmaf(wv.y, v1.y, wv.z * v2.y));
    a.z = fmaf(wv.x, v0.z, fmaf(wv.y, v1.z, wv.z * v2.z));
    a.w = fmaf(wv.x, v0.w, fmaf(wv.y, v1.w, wv.z * v2.w));
    uint32_t h0, l0, h1, l1, h2, l2, h3, l3;
    split_bf16(a.x, h0, l0); split_bf16(a.y, h1, l1);
    split_bf16(a.z, h2, l2); split_bf16(a.w, h3, l3);
    const size_t o = (size_t)n * CIN + D1_ + lane * 4;
    *(uint2*)(g_x1h + o) = make_uint2(h0 | (h1 << 16), h2 | (h3 << 16));
    *(uint2*)(g_x1l + o) = make_uint2(l0 | (l1 << 16), l2 | (l3 << 16));
}

// ---------------------------------------------------------------------------
// Warp-MMA GEMM: CTA 128x128, 256 threads, grid (2,512), K-chunk 64.
// SINGLE smem buffer (64KB) + __launch_bounds__(256,2) -> 2 CTAs/SM.
// Cross-CTA overlap hides the load/barrier gaps that a double buffer used
// to hide (tensor was 61% at 1 CTA/SM). Term-major MMA ordering kept.
// ---------------------------------------------------------------------------
#define MMA_SMEM (65536 + 1024)

template <int LAYER>
__global__ void __launch_bounds__(256, 2) k_mma() {
    constexpr int K  = (LAYER == 1) ? CIN : CO;
    constexpr int KT = K / 64;
    const __nv_bfloat16* xh = (LAYER == 1) ? g_x1h : g_x2h;
    const __nv_bfloat16* xl = (LAYER == 1) ? g_x1l : g_x2l;
    const __nv_bfloat16* wh = (LAYER == 1) ? g_w1h : g_w2h;
    const __nv_bfloat16* wl = (LAYER == 1) ? g_w1l : g_w2l;
    float* C = g_y1;

    extern __shared__ uint8_t dsm[];
    const uint32_t sbase = (smem_u32(dsm) + 1023) & ~1023u;

    const int tid  = threadIdx.x, wid = tid >> 5, lane = tid & 31;
    const int m0   = blockIdx.y << 7;     // sample tile (slow axis)
    const int n0   = blockIdx.x << 7;     // channel tile (fast axis, pair shares X)
    const int wm   = wid & 3, wn = wid >> 2;

    auto stage = [&](int kt) {
        const int k0 = kt * 64;
#pragma unroll
        for (int i = 0; i < 16; i++) {
            const int q = tid + i * 256;
            const int sel = q >> 10;
            const int r = (q & 1023) >> 3, c = q & 7;
            const __nv_bfloat16* src;
            if      (sel == 0) src = xh + (size_t)(m0 + r) * K + k0 + c * 8;
            else if (sel == 1) src = xl + (size_t)(m0 + r) * K + k0 + c * 8;
            else if (sel == 2) src = wh + (size_t)(n0 + r) * K + k0 + c * 8;
            else               src = wl + (size_t)(n0 + r) * K + k0 + c * 8;
            const uint32_t dst = sbase + sel * 16384 + r * 128 + (((uint32_t)(c ^ (r & 7))) << 4);
            asm volatile("cp.async.cg.shared.global [%0], [%1], 16;" :: "r"(dst), "l"(src));
        }
        asm volatile("cp.async.commit_group;");
    };

    int rA[2], cAx = lane >> 4;
#pragma unroll
    for (int s = 0; s < 2; s++)
        rA[s] = wm * 32 + s * 16 + (lane & 7) + ((lane >> 3) & 1) * 8;
    int rB[4], cBx = (lane >> 3) & 1;
#pragma unroll
    for (int jj = 0; jj < 4; jj++)
        rB[jj] = wn * 64 + (jj * 2 + (lane >> 4)) * 8 + (lane & 7);

    float acc[2][8][4];
#pragma unroll
    for (int s = 0; s < 2; s++)
#pragma unroll
        for (int j = 0; j < 8; j++)
#pragma unroll
            for (int v = 0; v < 4; v++) acc[s][j][v] = 0.f;

#pragma unroll 1
    for (int kt = 0; kt < KT; kt++) {
        stage(kt);
        asm volatile("cp.async.wait_group 0;");
        __syncthreads();
        const uint32_t bXh = sbase, bXl = sbase + 16384, bWh = sbase + 32768, bWl = sbase + 49152;
#pragma unroll
        for (int ks = 0; ks < 4; ks++) {
            uint32_t ah[2][4], al[2][4], bh[4][4], bl[4][4];
#pragma unroll
            for (int s = 0; s < 2; s++) {
                const uint32_t off = rA[s] * 128 + (((uint32_t)((ks * 2 + cAx) ^ (rA[s] & 7))) << 4);
                asm volatile("ldmatrix.sync.aligned.m8n8.x4.shared.b16 {%0,%1,%2,%3}, [%4];"
                    : "=r"(ah[s][0]), "=r"(ah[s][1]), "=r"(ah[s][2]), "=r"(ah[s][3]) : "r"(bXh + off));
                asm volatile("ldmatrix.sync.aligned.m8n8.x4.shared.b16 {%0,%1,%2,%3}, [%4];"
                    : "=r"(al[s][0]), "=r"(al[s][1]), "=r"(al[s][2]), "=r"(al[s][3]) : "r"(bXl + off));
            }
#pragma unroll
            for (int jj = 0; jj < 4; jj++) {
                const uint32_t off = rB[jj] * 128 + (((uint32_t)((ks * 2 + cBx) ^ (rB[jj] & 7))) << 4);
                asm volatile("ldmatrix.sync.aligned.m8n8.x4.shared.b16 {%0,%1,%2,%3}, [%4];"
                    : "=r"(bh[jj][0]), "=r"(bh[jj][1]), "=r"(bh[jj][2]), "=r"(bh[jj][3]) : "r"(bWh + off));
                asm volatile("ldmatrix.sync.aligned.m8n8.x4.shared.b16 {%0,%1,%2,%3}, [%4];"
                    : "=r"(bl[jj][0]), "=r"(bl[jj][1]), "=r"(bl[jj][2]), "=r"(bl[jj][3]) : "r"(bWl + off));
            }
#define MMA_(A, Bf, CC) asm volatile( \
    "mma.sync.aligned.m16n8k16.row.col.f32.bf16.bf16.f32 " \
    "{%0,%1,%2,%3}, {%4,%5,%6,%7}, {%8,%9}, {%0,%1,%2,%3};" \
    : "+f"((CC)[0]), "+f"((CC)[1]), "+f"((CC)[2]), "+f"((CC)[3]) \
    : "r"((A)[0]), "r"((A)[1]), "r"((A)[2]), "r"((A)[3]), "r"((Bf)[0]), "r"((Bf)[1]))
            // term 1: Xh * Wh  (16 independent accumulators back-to-back)
#pragma unroll
            for (int s = 0; s < 2; s++)
#pragma unroll
                for (int j = 0; j < 8; j++)
                    MMA_(ah[s], (&bh[j >> 1][(j & 1) * 2]), acc[s][j]);
            // term 2: Xl * Wh
#pragma unroll
            for (int s = 0; s < 2; s++)
#pragma unroll
                for (int j = 0; j < 8; j++)
                    MMA_(al[s], (&bh[j >> 1][(j & 1) * 2]), acc[s][j]);
            // term 3: Xh * Wl
#pragma unroll
            for (int s = 0; s < 2; s++)
#pragma unroll
                for (int j = 0; j < 8; j++)
                    MMA_(ah[s], (&bl[j >> 1][(j & 1) * 2]), acc[s][j]);
#undef MMA_
        }
        __syncthreads();
    }

    // ---- lean epilogue: direct fp32 stores to C[n,256] ----
#pragma unroll
    for (int s = 0; s < 2; s++) {
        const int m = m0 + wm * 32 + s * 16 + (lane >> 2);
#pragma unroll
        for (int j = 0; j < 8; j++) {
            const int n = n0 + wn * 64 + j * 8 + (lane & 3) * 2;
            *(float2*)(C + (size_t)m * CO + n)       = make_float2(acc[s][j][0], acc[s][j][1]);
            *(float2*)(C + (size_t)(m + 8) * CO + n) = make_float2(acc[s][j][2], acc[s][j][3]);
        }
    }
}

// ---------------------------------------------------------------------------
// k_stats: per-channel partials over y [n,256]; deterministic.
// ---------------------------------------------------------------------------
__global__ void __launch_bounds__(256) k_stats() {
    __shared__ float4 ss[256], qq[256];
    const int j = blockIdx.x, t = threadIdx.x;
    const int cq = t & 63, rq = t >> 6;
    const float4* y = (const float4*)g_y1;
    float4 s = make_float4(0, 0, 0, 0), q = make_float4(0, 0, 0, 0);
    for (int i = 0; i < 64; i++) {
        const int row = j * 256 + rq * 64 + i;
        const float4 v = y[(size_t)row * 64 + cq];
        s.x += v.x; s.y += v.y; s.z += v.z; s.w += v.w;
        q.x = fmaf(v.x, v.x, q.x); q.y = fmaf(v.y, v.y, q.y);
        q.z = fmaf(v.z, v.z, q.z); q.w = fmaf(v.w, v.w, q.w);
    }
    ss[t] = s; qq[t] = q;
    __syncthreads();
    if (t < 64) {
        float4 a = ss[t], b = ss[t + 64], c = ss[t + 128], d = ss[t + 192];
        float4 e = qq[t], f = qq[t + 64], g = qq[t + 128], h = qq[t + 192];
        float4 so = make_float4((a.x + b.x) + (c.x + d.x), (a.y + b.y) + (c.y + d.y),
                                (a.z + b.z) + (c.z + d.z), (a.w + b.w) + (c.w + d.w));
        float4 qo = make_float4((e.x + f.x) + (g.x + h.x), (e.y + f.y) + (g.y + h.y),
                                (e.z + f.z) + (g.z + h.z), (e.w + f.w) + (g.w + h.w));
        *(float4*)&g_psum[j * 256 + t * 4] = so;
        *(float4*)&g_psq[j * 256 + t * 4]  = qo;
    }
}

// ---------------------------------------------------------------------------
// fold: reduce 256 partials/channel -> folded BN affine
// ---------------------------------------------------------------------------
__global__ void k_fold(const float* __restrict__ gamma, const float* __restrict__ beta,
                       int layer) {
    const int c = threadIdx.x;
    float s = 0.f, q = 0.f;
    for (int j = 0; j < 256; j++) {
        s += g_psum[j * 256 + c];
        q += g_psq[j * 256 + c];
    }
    const float mean = s * (1.f / (float)NS);
    const float var  = q * (1.f / (float)NS) - mean * mean;
    const float a = gamma[c] * rsqrtf(var + 1e-5f);
    const float b = beta[c] - mean * a;
    if (layer == 1) { g_a1[c] = a; g_b1[c] = b; }
    else            { g_a2[c] = a; g_b2[c] = b; }
}

// ---------------------------------------------------------------------------
// x2 = split(relu(a1*y1 + b1))
// ---------------------------------------------------------------------------
__global__ void __launch_bounds__(256) k_x2() {
    const size_t i = (size_t)blockIdx.x * 256 + threadIdx.x;
    const size_t row = i >> 6;
    const int cq = (int)(i & 63), c0 = cq * 4;
    float4 v = ((const float4*)g_y1)[row * 64 + cq];
    const float4 a = *(const float4*)&g_a1[c0];
    const float4 b = *(const float4*)&g_b1[c0];
    v.x = fmaxf(fmaf(a.x, v.x, b.x), 0.f);
    v.y = fmaxf(fmaf(a.y, v.y, b.y), 0.f);
    v.z = fmaxf(fmaf(a.z, v.z, b.z), 0.f);
    v.w = fmaxf(fmaf(a.w, v.w, b.w), 0.f);
    uint32_t h0, l0, h1, l1, h2, l2, h3, l3;
    split_bf16(v.x, h0, l0); split_bf16(v.y, h1, l1);
    split_bf16(v.z, h2, l2); split_bf16(v.w, h3, l3);
    const size_t o = row * CO + c0;
    *(uint2*)(g_x2h + o) = make_uint2(h0 | (h1 << 16), h2 | (h3 << 16));
    *(uint2*)(g_x2l + o) = make_uint2(l0 | (l1 << 16), l2 | (l3 << 16));
}

// ---------------------------------------------------------------------------
// finalize: out[b,o,n] = relu(a2*y2[n,o] + b2)
// ---------------------------------------------------------------------------
__global__ void k_finalize(float* __restrict__ out) {
    __shared__ float t[32][33];
    const int b = blockIdx.z, o0 = blockIdx.y * 32, n0 = blockIdx.x * 32;
    const int tx = threadIdx.x, ty = threadIdx.y;
    const float a = g_a2[o0 + tx], bb = g_b2[o0 + tx];
#pragma unroll
    for (int i = 0; i < 4; i++) {
        const int n = n0 + ty + i * 8;
        const float v = g_y1[(size_t)(b * NPT + n) * CO + o0 + tx];
        t[tx][ty + i * 8] = fmaxf(fmaf(a, v, bb), 0.f);
    }
    __syncthreads();
#pragma unroll
    for (int i = 0; i < 4; i++)
        out[((size_t)b * CO + o0 + ty + i * 8) * NPT + n0 + tx] = t[ty + i * 8][tx];
}

// ---------------------------------------------------------------------------
// Launch
// ---------------------------------------------------------------------------
extern "C" void kernel_launch(void* const* d_in, const int* in_sizes, int n_in,
                              void* d_out, int out_size) {
    const float* xyz1    = (const float*)d_in[0];
    const float* xyz2    = (const float*)d_in[1];
    const float* points1 = (const float*)d_in[2];
    const float* points2 = (const float*)d_in[3];
    const float* W1      = (const float*)d_in[4];
    const float* g1      = (const float*)d_in[6];
    const float* be1     = (const float*)d_in[7];
    const float* W2      = (const float*)d_in[8];
    const float* g2      = (const float*)d_in[10];
    const float* be2     = (const float*)d_in[11];
    float* out = (float*)d_out;

    cudaFuncSetAttribute(k_mma<1>, cudaFuncAttributeMaxDynamicSharedMemorySize, MMA_SMEM);
    cudaFuncSetAttribute(k_mma<2>, cudaFuncAttributeMaxDynamicSharedMemorySize, MMA_SMEM);

    k_prep<<<19072, 256>>>(W1, W2, points2, points1);
    k_nn<<<dim3(32, 16), 256>>>(xyz1, xyz2);
    k_gather<<<8192, 256>>>();
    k_mma<1><<<dim3(2, 512), 256, MMA_SMEM>>>();
    k_stats<<<256, 256>>>();
    k_fold<<<1, 256>>>(g1, be1, 1);
    k_x2<<<16384, 256>>>();
    k_mma<2><<<dim3(2, 512), 256, MMA_SMEM>>>();
    k_stats<<<256, 256>>>();
    k_fold<<<1, 256>>>(g2, be2, 2);
    k_finalize<<<dim3(128, 8, 16), dim3(32, 8)>>>(out);
}

// round 14
// speedup vs baseline: 1.1345x; 1.0010x over previous
#include <cuda_runtime.h>
#include <cuda_bf16.h>
#include <cstdint>
#include <cstddef>

#define B_   16
#define NPT  4096
#define SPT  1024
#define D1_  256
#define D2_  128
#define CIN  384
#define CO   256
#define NS   (B_*NPT)   // 65536

// ---------------------------------------------------------------------------
// Scratch
// ---------------------------------------------------------------------------
__device__ float         g_p2t[B_ * SPT * D2_];
__device__ __nv_bfloat16 g_x1h[(size_t)NS * CIN];
__device__ __nv_bfloat16 g_x1l[(size_t)NS * CIN];
__device__ __nv_bfloat16 g_x2h[(size_t)NS * CO];
__device__ __nv_bfloat16 g_x2l[(size_t)NS * CO];
__device__ float         g_y1[(size_t)NS * CO];     // y1, then reused as y2
__device__ __nv_bfloat16 g_w1h[CO * CIN], g_w1l[CO * CIN];
__device__ __nv_bfloat16 g_w2h[CO * CO],  g_w2l[CO * CO];
__device__ float g_psum[256 * 256], g_psq[256 * 256]; // [rowblock][channel] partials
__device__ float g_a1[CO], g_b1[CO], g_a2[CO], g_b2[CO];
__device__ float4 g_nnw4[NS];   // 3 normalized weights per query
__device__ int4   g_nni4[NS];   // 3 neighbor indices per query

__device__ __forceinline__ uint32_t smem_u32(const void* p) {
    uint32_t a;
    asm("{ .reg .u64 t; cvta.to.shared.u64 t, %1; cvt.u32.u64 %0, t; }" : "=r"(a) : "l"(p));
    return a;
}
__device__ __forceinline__ void split_bf16(float a, uint32_t& h, uint32_t& l) {
    __nv_bfloat16 hb = __float2bfloat16(a);
    __nv_bfloat16 lb = __float2bfloat16(a - __bfloat162float(hb));
    h = (uint32_t)__bfloat16_as_ushort(hb);
    l = (uint32_t)__bfloat16_as_ushort(lb);
}

// ---------------------------------------------------------------------------
// k_prep: fused W-split + points2 transpose + points1 transpose/split.
// ---------------------------------------------------------------------------
__global__ void __launch_bounds__(256) k_prep(const float* __restrict__ W1,
                                              const float* __restrict__ W2,
                                              const float* __restrict__ p2,
                                              const float* __restrict__ p1) {
    __shared__ float t[32][33];
    const int bi = blockIdx.x, tid = threadIdx.x;
    const int tx = tid & 31, ty = tid >> 5;

    if (bi < 640) {                       // ---- W split ----
        const int i = bi * 256 + tid;
        uint32_t h, l;
        if (i < CO * CIN) {
            split_bf16(W1[i], h, l);
            g_w1h[i] = __ushort_as_bfloat16((unsigned short)h);
            g_w1l[i] = __ushort_as_bfloat16((unsigned short)l);
        } else {
            const int j = i - CO * CIN;
            split_bf16(W2[j], h, l);
            g_w2h[j] = __ushort_as_bfloat16((unsigned short)h);
            g_w2l[j] = __ushort_as_bfloat16((unsigned short)l);
        }
        return;
    }
    if (bi < 2688) {                      // ---- tp2: [B,D2,S] -> [B,S,D2] ----
        const int idx = bi - 640;
        const int b = idx >> 7, rem = idx & 127;
        const int c0 = (rem >> 5) * 32, s0 = (rem & 31) * 32;
#pragma unroll
        for (int i = 0; i < 4; i++)
            t[ty + i * 8][tx] = p2[((size_t)b * D2_ + c0 + ty + i * 8) * SPT + s0 + tx];
        __syncthreads();
#pragma unroll
        for (int i = 0; i < 4; i++)
            g_p2t[((size_t)b * SPT + s0 + ty + i * 8) * D2_ + c0 + tx] = t[tx][ty + i * 8];
        return;
    }
    {                                     // ---- tp1: X1 cols [0,256) ----
        const int idx = bi - 2688;
        const int b = idx >> 10, rem = idx & 1023;
        const int c0 = (rem >> 7) * 32, n0 = (rem & 127) * 32;
#pragma unroll
        for (int i = 0; i < 4; i++)
            t[ty + i * 8][tx] = p1[((size_t)b * D1_ + c0 + ty + i * 8) * NPT + n0 + tx];
        __syncthreads();
#pragma unroll
        for (int w = 0; w < 2; w++) {
            const int v = w * 256 + tid;
            const int n = v >> 4, u = v & 15;
            uint32_t h0, l0, h1, l1;
            split_bf16(t[2 * u][n], h0, l0);
            split_bf16(t[2 * u + 1][n], h1, l1);
            const size_t a = (size_t)(b * NPT + n0 + n) * CIN + c0 + 2 * u;
            *(uint32_t*)(g_x1h + a) = h0 | (h1 << 16);
            *(uint32_t*)(g_x1l + a) = l0 | (l1 << 16);
        }
    }
}

// ---------------------------------------------------------------------------
// k_nn: split-S 3-NN (2 threads/query, rare-branch insertion, smem merge).
// ---------------------------------------------------------------------------
__global__ void __launch_bounds__(256) k_nn(const float* __restrict__ xyz1,
                                            const float* __restrict__ xyz2) {
    __shared__ float4 s2[SPT];
    __shared__ float sd[3][128];
    __shared__ int   si[3][128];
    const int b = blockIdx.y, tid = threadIdx.x;
    const int q = tid & 127, half = tid >> 7;
    const int n = blockIdx.x * 128 + q;
    for (int i = tid; i < SPT; i += 256) {
        const float x = xyz2[(size_t)b * 3072 + i];
        const float y = xyz2[(size_t)b * 3072 + 1024 + i];
        const float z = xyz2[(size_t)b * 3072 + 2048 + i];
        s2[i] = make_float4(x, y, z, fmaf(x, x, fmaf(y, y, z * z)));
    }
    __syncthreads();

    const float px = xyz1[((size_t)b * 3 + 0) * NPT + n];
    const float py = xyz1[((size_t)b * 3 + 1) * NPT + n];
    const float pz = xyz1[((size_t)b * 3 + 2) * NPT + n];
    const float mx = -2.f * px, my = -2.f * py, mz = -2.f * pz;
    const float a2 = fmaf(px, px, fmaf(py, py, pz * pz));

    float d0 = 1e30f, d1 = 1e30f, d2 = 1e30f;
    int   i0 = 0, i1 = 0, i2 = 0;
    const int sbeg = half << 9;
#pragma unroll 4
    for (int s = sbeg; s < sbeg + 512; s++) {
        const float4 v = s2[s];
        const float d = fmaf(mx, v.x, fmaf(my, v.y, fmaf(mz, v.z, v.w)));
        if (d < d2) {
            const bool p0 = d < d0, p1 = d < d1;
            i2 = p1 ? i1 : s;
            d2 = p1 ? d1 : d;
            i1 = p0 ? i0 : (p1 ? s : i1);
            d1 = p0 ? d0 : (p1 ? d : d1);
            i0 = p0 ? s : i0;
            d0 = p0 ? d : d0;
        }
    }
    if (half) {
        sd[0][q] = d0; sd[1][q] = d1; sd[2][q] = d2;
        si[0][q] = i0; si[1][q] = i1; si[2][q] = i2;
    }
    __syncthreads();
    if (!half) {
        float b0 = sd[0][q], b1 = sd[1][q], b2 = sd[2][q];
        int   j0 = si[0][q], j1 = si[1][q], j2 = si[2][q];
        float m0, m1, m2; int o0, o1, o2;
        bool t = b0 < d0;                       // ties -> lower-index half (d)
        m0 = t ? b0 : d0; o0 = t ? j0 : i0;
        if (t) { b0 = b1; j0 = j1; b1 = b2; j1 = j2; }
        else   { d0 = d1; i0 = i1; d1 = d2; i1 = i2; }
        t = b0 < d0;
        m1 = t ? b0 : d0; o1 = t ? j0 : i0;
        if (t) { b0 = b1; j0 = j1; }
        else   { d0 = d1; i0 = i1; }
        t = b0 < d0;
        m2 = t ? b0 : d0; o2 = t ? j0 : i0;

        const float f0 = sqrtf(fmaxf(m0 + a2, 0.f));
        const float f1 = sqrtf(fmaxf(m1 + a2, 0.f));
        const float f2 = sqrtf(fmaxf(m2 + a2, 0.f));
        float w0 = 1.f / (f0 + 1e-10f);
        float w1 = 1.f / (f1 + 1e-10f);
        float w2 = 1.f / (f2 + 1e-10f);
        const float inv = 1.f / (w0 + w1 + w2);
        const int g = b * NPT + n;
        g_nnw4[g] = make_float4(w0 * inv, w1 * inv, w2 * inv, 0.f);
        g_nni4[g] = make_int4(o0, o1, o2, 0);
    }
}

// ---------------------------------------------------------------------------
// k_gather: warp per query; register accumulation; bf16 hi/lo out.
// ---------------------------------------------------------------------------
__global__ void __launch_bounds__(256) k_gather() {
    const int wid = threadIdx.x >> 5, lane = threadIdx.x & 31;
    const int n = blockIdx.x * 8 + wid;
    const int b = n >> 12;
    const float4 wv = g_nnw4[n];
    const int4   iv = g_nni4[n];
    const float* p2t = g_p2t + (size_t)b * SPT * D2_;
    const float4 v0 = *(const float4*)(p2t + (size_t)iv.x * D2_ + lane * 4);
    const float4 v1 = *(const float4*)(p2t + (size_t)iv.y * D2_ + lane * 4);
    const float4 v2 = *(const float4*)(p2t + (size_t)iv.z * D2_ + lane * 4);
    float4 a;
    a.x = fmaf(wv.x, v0.x, fmaf(wv.y, v1.x, wv.z * v2.x));
    a.y = fmaf(wv.x, v0.y, fmaf(wv.y, v1.y, wv.z * v2.y));
    a.z = fmaf(wv.x, v0.z, fmaf(wv.y, v1.z, wv.z * v2.z));
    a.w = fmaf(wv.x, v0.w, fmaf(wv.y, v1.w, wv.z * v2.w));
    uint32_t h0, l0, h1, l1, h2, l2, h3, l3;
    split_bf16(a.x, h0, l0); split_bf16(a.y, h1, l1);
    split_bf16(a.z, h2, l2); split_bf16(a.w, h3, l3);
    const size_t o = (size_t)n * CIN + D1_ + lane * 4;
    *(uint2*)(g_x1h + o) = make_uint2(h0 | (h1 << 16), h2 | (h3 << 16));
    *(uint2*)(g_x1l + o) = make_uint2(l0 | (l1 << 16), l2 | (l3 << 16));
}

// ---------------------------------------------------------------------------
// Warp-MMA GEMM: CTA 128(M) x 64(N), 256 threads (warps 4Mx2N, warp 32x32),
// K-chunk 64, DOUBLE-buffered 96KB smem + __launch_bounds__(256,2):
// intra-CTA cp.async pipelining AND 2 CTAs/SM cross-overlap.
// Grid (4, 512): 4 adjacent CTAs share each X tile via L2.
// Buffer layout: Xh 16K | Xl 16K | Wh 8K | Wl 8K = 48KB.
// ---------------------------------------------------------------------------
#define BUFSZ 49152
#define MMA_SMEM (2 * BUFSZ + 1024)

template <int LAYER>
__global__ void __launch_bounds__(256, 2) k_mma() {
    constexpr int K  = (LAYER == 1) ? CIN : CO;
    constexpr int KT = K / 64;
    const __nv_bfloat16* xh = (LAYER == 1) ? g_x1h : g_x2h;
    const __nv_bfloat16* xl = (LAYER == 1) ? g_x1l : g_x2l;
    const __nv_bfloat16* wh = (LAYER == 1) ? g_w1h : g_w2h;
    const __nv_bfloat16* wl = (LAYER == 1) ? g_w1l : g_w2l;
    float* C = g_y1;

    extern __shared__ uint8_t dsm[];
    const uint32_t sbase = (smem_u32(dsm) + 1023) & ~1023u;

    const int tid  = threadIdx.x, wid = tid >> 5, lane = tid & 31;
    const int m0   = blockIdx.y << 7;     // sample tile (slow axis)
    const int n0   = blockIdx.x << 6;     // channel tile (fast axis, 4 share X)
    const int wm   = wid & 3, wn = wid >> 2;

    auto stage = [&](int kt) {
        const uint32_t base = sbase + (kt & 1) * BUFSZ;
        const int k0 = kt * 64;
        // X h+l: 2048 segs of 16B
#pragma unroll
        for (int i = 0; i < 8; i++) {
            const int q = tid + i * 256;
            const int sel = q >> 10;              // 0 xh, 1 xl
            const int r = (q & 1023) >> 3, c = q & 7;
            const __nv_bfloat16* src = ((sel == 0) ? xh : xl) + (size_t)(m0 + r) * K + k0 + c * 8;
            const uint32_t dst = base + sel * 16384 + r * 128 + (((uint32_t)(c ^ (r & 7))) << 4);
            asm volatile("cp.async.cg.shared.global [%0], [%1], 16;" :: "r"(dst), "l"(src));
        }
        // W h+l: 64 rows -> 1024 segs of 16B
#pragma unroll
        for (int i = 0; i < 4; i++) {
            const int q = tid + i * 256;
            const int sel = q >> 9;               // 0 wh, 1 wl
            const int r = (q & 511) >> 3, c = q & 7;
            const __nv_bfloat16* src = ((sel == 0) ? wh : wl) + (size_t)(n0 + r) * K + k0 + c * 8;
            const uint32_t dst = base + 32768 + sel * 8192 + r * 128 + (((uint32_t)(c ^ (r & 7))) << 4);
            asm volatile("cp.async.cg.shared.global [%0], [%1], 16;" :: "r"(dst), "l"(src));
        }
        asm volatile("cp.async.commit_group;");
    };

    int rA[2], cAx = lane >> 4;
#pragma unroll
    for (int s = 0; s < 2; s++)
        rA[s] = wm * 32 + s * 16 + (lane & 7) + ((lane >> 3) & 1) * 8;
    int rB[2], cBx = (lane >> 3) & 1;
#pragma unroll
    for (int jj = 0; jj < 2; jj++)
        rB[jj] = wn * 32 + (jj * 2 + (lane >> 4)) * 8 + (lane & 7);

    float acc[2][4][4];
#pragma unroll
    for (int s = 0; s < 2; s++)
#pragma unroll
        for (int j = 0; j < 4; j++)
#pragma unroll
            for (int v = 0; v < 4; v++) acc[s][j][v] = 0.f;

    stage(0);
#pragma unroll 1
    for (int kt = 0; kt < KT; kt++) {
        if (kt + 1 < KT) { stage(kt + 1); asm volatile("cp.async.wait_group 1;"); }
        else             { asm volatile("cp.async.wait_group 0;"); }
        __syncthreads();
        const uint32_t base = sbase + (kt & 1) * BUFSZ;
        const uint32_t bXh = base, bXl = base + 16384, bWh = base + 32768, bWl = base + 40960;
#pragma unroll
        for (int ks = 0; ks < 4; ks++) {
            uint32_t ah[2][4], al[2][4], bh[2][4], bl[2][4];
#pragma unroll
            for (int s = 0; s < 2; s++) {
                const uint32_t off = rA[s] * 128 + (((uint32_t)((ks * 2 + cAx) ^ (rA[s] & 7))) << 4);
                asm volatile("ldmatrix.sync.aligned.m8n8.x4.shared.b16 {%0,%1,%2,%3}, [%4];"
                    : "=r"(ah[s][0]), "=r"(ah[s][1]), "=r"(ah[s][2]), "=r"(ah[s][3]) : "r"(bXh + off));
                asm volatile("ldmatrix.sync.aligned.m8n8.x4.shared.b16 {%0,%1,%2,%3}, [%4];"
                    : "=r"(al[s][0]), "=r"(al[s][1]), "=r"(al[s][2]), "=r"(al[s][3]) : "r"(bXl + off));
            }
#pragma unroll
            for (int jj = 0; jj < 2; jj++) {
                const uint32_t off = rB[jj] * 128 + (((uint32_t)((ks * 2 + cBx) ^ (rB[jj] & 7))) << 4);
                asm volatile("ldmatrix.sync.aligned.m8n8.x4.shared.b16 {%0,%1,%2,%3}, [%4];"
                    : "=r"(bh[jj][0]), "=r"(bh[jj][1]), "=r"(bh[jj][2]), "=r"(bh[jj][3]) : "r"(bWh + off));
                asm volatile("ldmatrix.sync.aligned.m8n8.x4.shared.b16 {%0,%1,%2,%3}, [%4];"
                    : "=r"(bl[jj][0]), "=r"(bl[jj][1]), "=r"(bl[jj][2]), "=r"(bl[jj][3]) : "r"(bWl + off));
            }
#define MMA_(A, Bf, CC) asm volatile( \
    "mma.sync.aligned.m16n8k16.row.col.f32.bf16.bf16.f32 " \
    "{%0,%1,%2,%3}, {%4,%5,%6,%7}, {%8,%9}, {%0,%1,%2,%3};" \
    : "+f"((CC)[0]), "+f"((CC)[1]), "+f"((CC)[2]), "+f"((CC)[3]) \
    : "r"((A)[0]), "r"((A)[1]), "r"((A)[2]), "r"((A)[3]), "r"((Bf)[0]), "r"((Bf)[1]))
            // term-major: 8 independent accumulators per sweep
#pragma unroll
            for (int s = 0; s < 2; s++)
#pragma unroll
                for (int j = 0; j < 4; j++)
                    MMA_(ah[s], (&bh[j >> 1][(j & 1) * 2]), acc[s][j]);
#pragma unroll
            for (int s = 0; s < 2; s++)
#pragma unroll
                for (int j = 0; j < 4; j++)
                    MMA_(al[s], (&bh[j >> 1][(j & 1) * 2]), acc[s][j]);
#pragma unroll
            for (int s = 0; s < 2; s++)
#pragma unroll
                for (int j = 0; j < 4; j++)
                    MMA_(ah[s], (&bl[j >> 1][(j & 1) * 2]), acc[s][j]);
#undef MMA_
        }
        __syncthreads();
    }

    // ---- lean epilogue: direct fp32 stores to C[n,256] ----
#pragma unroll
    for (int s = 0; s < 2; s++) {
        const int m = m0 + wm * 32 + s * 16 + (lane >> 2);
#pragma unroll
        for (int j = 0; j < 4; j++) {
            const int n = n0 + wn * 32 + j * 8 + (lane & 3) * 2;
            *(float2*)(C + (size_t)m * CO + n)       = make_float2(acc[s][j][0], acc[s][j][1]);
            *(float2*)(C + (size_t)(m + 8) * CO + n) = make_float2(acc[s][j][2], acc[s][j][3]);
        }
    }
}

// ---------------------------------------------------------------------------
// k_stats: per-channel partials over y [n,256]; deterministic.
// ---------------------------------------------------------------------------
__global__ void __launch_bounds__(256) k_stats() {
    __shared__ float4 ss[256], qq[256];
    const int j = blockIdx.x, t = threadIdx.x;
    const int cq = t & 63, rq = t >> 6;
    const float4* y = (const float4*)g_y1;
    float4 s = make_float4(0, 0, 0, 0), q = make_float4(0, 0, 0, 0);
    for (int i = 0; i < 64; i++) {
        const int row = j * 256 + rq * 64 + i;
        const float4 v = y[(size_t)row * 64 + cq];
        s.x += v.x; s.y += v.y; s.z += v.z; s.w += v.w;
        q.x = fmaf(v.x, v.x, q.x); q.y = fmaf(v.y, v.y, q.y);
        q.z = fmaf(v.z, v.z, q.z); q.w = fmaf(v.w, v.w, q.w);
    }
    ss[t] = s; qq[t] = q;
    __syncthreads();
    if (t < 64) {
        float4 a = ss[t], b = ss[t + 64], c = ss[t + 128], d = ss[t + 192];
        float4 e = qq[t], f = qq[t + 64], g = qq[t + 128], h = qq[t + 192];
        float4 so = make_float4((a.x + b.x) + (c.x + d.x), (a.y + b.y) + (c.y + d.y),
                                (a.z + b.z) + (c.z + d.z), (a.w + b.w) + (c.w + d.w));
        float4 qo = make_float4((e.x + f.x) + (g.x + h.x), (e.y + f.y) + (g.y + h.y),
                                (e.z + f.z) + (g.z + h.z), (e.w + f.w) + (g.w + h.w));
        *(float4*)&g_psum[j * 256 + t * 4] = so;
        *(float4*)&g_psq[j * 256 + t * 4]  = qo;
    }
}

// ---------------------------------------------------------------------------
// fold: reduce 256 partials/channel -> folded BN affine
// ---------------------------------------------------------------------------
__global__ void k_fold(const float* __restrict__ gamma, const float* __restrict__ beta,
                       int layer) {
    const int c = threadIdx.x;
    float s = 0.f, q = 0.f;
    for (int j = 0; j < 256; j++) {
        s += g_psum[j * 256 + c];
        q += g_psq[j * 256 + c];
    }
    const float mean = s * (1.f / (float)NS);
    const float var  = q * (1.f / (float)NS) - mean * mean;
    const float a = gamma[c] * rsqrtf(var + 1e-5f);
    const float b = beta[c] - mean * a;
    if (layer == 1) { g_a1[c] = a; g_b1[c] = b; }
    else            { g_a2[c] = a; g_b2[c] = b; }
}

// ---------------------------------------------------------------------------
// x2 = split(relu(a1*y1 + b1))
// ---------------------------------------------------------------------------
__global__ void __launch_bounds__(256) k_x2() {
    const size_t i = (size_t)blockIdx.x * 256 + threadIdx.x;
    const size_t row = i >> 6;
    const int cq = (int)(i & 63), c0 = cq * 4;
    float4 v = ((const float4*)g_y1)[row * 64 + cq];
    const float4 a = *(const float4*)&g_a1[c0];
    const float4 b = *(const float4*)&g_b1[c0];
    v.x = fmaxf(fmaf(a.x, v.x, b.x), 0.f);
    v.y = fmaxf(fmaf(a.y, v.y, b.y), 0.f);
    v.z = fmaxf(fmaf(a.z, v.z, b.z), 0.f);
    v.w = fmaxf(fmaf(a.w, v.w, b.w), 0.f);
    uint32_t h0, l0, h1, l1, h2, l2, h3, l3;
    split_bf16(v.x, h0, l0); split_bf16(v.y, h1, l1);
    split_bf16(v.z, h2, l2); split_bf16(v.w, h3, l3);
    const size_t o = row * CO + c0;
    *(uint2*)(g_x2h + o) = make_uint2(h0 | (h1 << 16), h2 | (h3 << 16));
    *(uint2*)(g_x2l + o) = make_uint2(l0 | (l1 << 16), l2 | (l3 << 16));
}

// ---------------------------------------------------------------------------
// finalize: out[b,o,n] = relu(a2*y2[n,o] + b2)
// ---------------------------------------------------------------------------
__global__ void k_finalize(float* __restrict__ out) {
    __shared__ float t[32][33];
    const int b = blockIdx.z, o0 = blockIdx.y * 32, n0 = blockIdx.x * 32;
    const int tx = threadIdx.x, ty = threadIdx.y;
    const float a = g_a2[o0 + tx], bb = g_b2[o0 + tx];
#pragma unroll
    for (int i = 0; i < 4; i++) {
        const int n = n0 + ty + i * 8;
        const float v = g_y1[(size_t)(b * NPT + n) * CO + o0 + tx];
        t[tx][ty + i * 8] = fmaxf(fmaf(a, v, bb), 0.f);
    }
    __syncthreads();
#pragma unroll
    for (int i = 0; i < 4; i++)
        out[((size_t)b * CO + o0 + ty + i * 8) * NPT + n0 + tx] = t[ty + i * 8][tx];
}

// ---------------------------------------------------------------------------
// Launch
// ---------------------------------------------------------------------------
extern "C" void kernel_launch(void* const* d_in, const int* in_sizes, int n_in,
                              void* d_out, int out_size) {
    const float* xyz1    = (const float*)d_in[0];
    const float* xyz2    = (const float*)d_in[1];
    const float* points1 = (const float*)d_in[2];
    const float* points2 = (const float*)d_in[3];
    const float* W1      = (const float*)d_in[4];
    const float* g1      = (const float*)d_in[6];
    const float* be1     = (const float*)d_in[7];
    const float* W2      = (const float*)d_in[8];
    const float* g2      = (const float*)d_in[10];
    const float* be2     = (const float*)d_in[11];
    float* out = (float*)d_out;

    cudaFuncSetAttribute(k_mma<1>, cudaFuncAttributeMaxDynamicSharedMemorySize, MMA_SMEM);
    cudaFuncSetAttribute(k_mma<2>, cudaFuncAttributeMaxDynamicSharedMemorySize, MMA_SMEM);

    k_prep<<<19072, 256>>>(W1, W2, points2, points1);
    k_nn<<<dim3(32, 16), 256>>>(xyz1, xyz2);
    k_gather<<<8192, 256>>>();
    k_mma<1><<<dim3(4, 512), 256, MMA_SMEM>>>();
    k_stats<<<256, 256>>>();
    k_fold<<<1, 256>>>(g1, be1, 1);
    k_x2<<<16384, 256>>>();
    k_mma<2><<<dim3(4, 512), 256, MMA_SMEM>>>();
    k_stats<<<256, 256>>>();
    k_fold<<<1, 256>>>(g2, be2, 2);
    k_finalize<<<dim3(128, 8, 16), dim3(32, 8)>>>(out);
}

// round 15
// speedup vs baseline: 1.2680x; 1.1176x over previous
#include <cuda_runtime.h>
#include <cuda_fp16.h>
#include <cstdint>
#include <cstddef>

#define B_   16
#define NPT  4096
#define SPT  1024
#define D1_  256
#define D2_  128
#define CIN  384
#define CO   256
#define NS   (B_*NPT)   // 65536

// ---------------------------------------------------------------------------
// Scratch (fp16 operands: X split hi/lo, W single-term)
// ---------------------------------------------------------------------------
__device__ float  g_p2t[B_ * SPT * D2_];
__device__ __half g_x1h[(size_t)NS * CIN];
__device__ __half g_x1l[(size_t)NS * CIN];
__device__ __half g_x2h[(size_t)NS * CO];
__device__ __half g_x2l[(size_t)NS * CO];
__device__ float  g_y1[(size_t)NS * CO];            // y1, then reused as y2
__device__ __half g_w1[CO * CIN];
__device__ __half g_w2[CO * CO];
__device__ float g_psum[256 * 256], g_psq[256 * 256]; // [rowblock][channel]
__device__ float g_a1[CO], g_b1[CO], g_a2[CO], g_b2[CO];
__device__ float4 g_nnw4[NS];
__device__ int4   g_nni4[NS];

__device__ __forceinline__ uint32_t smem_u32(const void* p) {
    uint32_t a;
    asm("{ .reg .u64 t; cvta.to.shared.u64 t, %1; cvt.u32.u64 %0, t; }" : "=r"(a) : "l"(p));
    return a;
}
__device__ __forceinline__ void split_f16(float a, uint32_t& h, uint32_t& l) {
    __half hb = __float2half_rn(a);
    __half lb = __float2half_rn(a - __half2float(hb));
    h = (uint32_t)__half_as_ushort(hb);
    l = (uint32_t)__half_as_ushort(lb);
}

// ---------------------------------------------------------------------------
// k_prep: fused W-convert + points2 transpose + points1 transpose/split.
// blockIdx.x: [0,640) W convert | [640,2688) tp2 | [2688,19072) tp1
// ---------------------------------------------------------------------------
__global__ void __launch_bounds__(256) k_prep(const float* __restrict__ W1,
                                              const float* __restrict__ W2,
                                              const float* __restrict__ p2,
                                              const float* __restrict__ p1) {
    __shared__ float t[32][33];
    const int bi = blockIdx.x, tid = threadIdx.x;
    const int tx = tid & 31, ty = tid >> 5;

    if (bi < 640) {                       // ---- W convert (single fp16 term) ----
        const int i = bi * 256 + tid;
        if (i < CO * CIN) g_w1[i] = __float2half_rn(W1[i]);
        else              g_w2[i - CO * CIN] = __float2half_rn(W2[i - CO * CIN]);
        return;
    }
    if (bi < 2688) {                      // ---- tp2: [B,D2,S] -> [B,S,D2] ----
        const int idx = bi - 640;
        const int b = idx >> 7, rem = idx & 127;
        const int c0 = (rem >> 5) * 32, s0 = (rem & 31) * 32;
#pragma unroll
        for (int i = 0; i < 4; i++)
            t[ty + i * 8][tx] = p2[((size_t)b * D2_ + c0 + ty + i * 8) * SPT + s0 + tx];
        __syncthreads();
#pragma unroll
        for (int i = 0; i < 4; i++)
            g_p2t[((size_t)b * SPT + s0 + ty + i * 8) * D2_ + c0 + tx] = t[tx][ty + i * 8];
        return;
    }
    {                                     // ---- tp1: X1 cols [0,256) fp16 hi/lo ----
        const int idx = bi - 2688;
        const int b = idx >> 10, rem = idx & 1023;
        const int c0 = (rem >> 7) * 32, n0 = (rem & 127) * 32;
#pragma unroll
        for (int i = 0; i < 4; i++)
            t[ty + i * 8][tx] = p1[((size_t)b * D1_ + c0 + ty + i * 8) * NPT + n0 + tx];
        __syncthreads();
#pragma unroll
        for (int w = 0; w < 2; w++) {
            const int v = w * 256 + tid;
            const int n = v >> 4, u = v & 15;
            uint32_t h0, l0, h1, l1;
            split_f16(t[2 * u][n], h0, l0);
            split_f16(t[2 * u + 1][n], h1, l1);
            const size_t a = (size_t)(b * NPT + n0 + n) * CIN + c0 + 2 * u;
            *(uint32_t*)(g_x1h + a) = h0 | (h1 << 16);
            *(uint32_t*)(g_x1l + a) = l0 | (l1 << 16);
        }
    }
}

// ---------------------------------------------------------------------------
// k_nn: split-S 3-NN (2 threads/query, rare-branch insertion, smem merge).
// ---------------------------------------------------------------------------
__global__ void __launch_bounds__(256) k_nn(const float* __restrict__ xyz1,
                                            const float* __restrict__ xyz2) {
    __shared__ float4 s2[SPT];
    __shared__ float sd[3][128];
    __shared__ int   si[3][128];
    const int b = blockIdx.y, tid = threadIdx.x;
    const int q = tid & 127, half = tid >> 7;
    const int n = blockIdx.x * 128 + q;
    for (int i = tid; i < SPT; i += 256) {
        const float x = xyz2[(size_t)b * 3072 + i];
        const float y = xyz2[(size_t)b * 3072 + 1024 + i];
        const float z = xyz2[(size_t)b * 3072 + 2048 + i];
        s2[i] = make_float4(x, y, z, fmaf(x, x, fmaf(y, y, z * z)));
    }
    __syncthreads();

    const float px = xyz1[((size_t)b * 3 + 0) * NPT + n];
    const float py = xyz1[((size_t)b * 3 + 1) * NPT + n];
    const float pz = xyz1[((size_t)b * 3 + 2) * NPT + n];
    const float mx = -2.f * px, my = -2.f * py, mz = -2.f * pz;
    const float a2 = fmaf(px, px, fmaf(py, py, pz * pz));

    float d0 = 1e30f, d1 = 1e30f, d2 = 1e30f;
    int   i0 = 0, i1 = 0, i2 = 0;
    const int sbeg = half << 9;
#pragma unroll 4
    for (int s = sbeg; s < sbeg + 512; s++) {
        const float4 v = s2[s];
        const float d = fmaf(mx, v.x, fmaf(my, v.y, fmaf(mz, v.z, v.w)));
        if (d < d2) {
            const bool p0 = d < d0, p1 = d < d1;
            i2 = p1 ? i1 : s;
            d2 = p1 ? d1 : d;
            i1 = p0 ? i0 : (p1 ? s : i1);
            d1 = p0 ? d0 : (p1 ? d : d1);
            i0 = p0 ? s : i0;
            d0 = p0 ? d : d0;
        }
    }
    if (half) {
        sd[0][q] = d0; sd[1][q] = d1; sd[2][q] = d2;
        si[0][q] = i0; si[1][q] = i1; si[2][q] = i2;
    }
    __syncthreads();
    if (!half) {
        float b0 = sd[0][q], b1 = sd[1][q], b2 = sd[2][q];
        int   j0 = si[0][q], j1 = si[1][q], j2 = si[2][q];
        float m0, m1, m2; int o0, o1, o2;
        bool t = b0 < d0;                       // ties -> lower-index half (d)
        m0 = t ? b0 : d0; o0 = t ? j0 : i0;
        if (t) { b0 = b1; j0 = j1; b1 = b2; j1 = j2; }
        else   { d0 = d1; i0 = i1; d1 = d2; i1 = i2; }
        t = b0 < d0;
        m1 = t ? b0 : d0; o1 = t ? j0 : i0;
        if (t) { b0 = b1; j0 = j1; }
        else   { d0 = d1; i0 = i1; }
        t = b0 < d0;
        m2 = t ? b0 : d0; o2 = t ? j0 : i0;

        const float f0 = sqrtf(fmaxf(m0 + a2, 0.f));
        const float f1 = sqrtf(fmaxf(m1 + a2, 0.f));
        const float f2 = sqrtf(fmaxf(m2 + a2, 0.f));
        float w0 = 1.f / (f0 + 1e-10f);
        float w1 = 1.f / (f1 + 1e-10f);
        float w2 = 1.f / (f2 + 1e-10f);
        const float inv = 1.f / (w0 + w1 + w2);
        const int g = b * NPT + n;
        g_nnw4[g] = make_float4(w0 * inv, w1 * inv, w2 * inv, 0.f);
        g_nni4[g] = make_int4(o0, o1, o2, 0);
    }
}

// ---------------------------------------------------------------------------
// k_gather: warp per query; register accumulation; fp16 hi/lo out.
// ---------------------------------------------------------------------------
__global__ void __launch_bounds__(256) k_gather() {
    const int wid = threadIdx.x >> 5, lane = threadIdx.x & 31;
    const int n = blockIdx.x * 8 + wid;
    const int b = n >> 12;
    const float4 wv = g_nnw4[n];
    const int4   iv = g_nni4[n];
    const float* p2t = g_p2t + (size_t)b * SPT * D2_;
    const float4 v0 = *(const float4*)(p2t + (size_t)iv.x * D2_ + lane * 4);
    const float4 v1 = *(const float4*)(p2t + (size_t)iv.y * D2_ + lane * 4);
    const float4 v2 = *(const float4*)(p2t + (size_t)iv.z * D2_ + lane * 4);
    float4 a;
    a.x = fmaf(wv.x, v0.x, fmaf(wv.y, v1.x, wv.z * v2.x));
    a.y = fmaf(wv.x, v0.y, fmaf(wv.y, v1.y, wv.z * v2.y));
    a.z = fmaf(wv.x, v0.z, fmaf(wv.y, v1.z, wv.z * v2.z));
    a.w = fmaf(wv.x, v0.w, fmaf(wv.y, v1.w, wv.z * v2.w));
    uint32_t h0, l0, h1, l1, h2, l2, h3, l3;
    split_f16(a.x, h0, l0); split_f16(a.y, h1, l1);
    split_f16(a.z, h2, l2); split_f16(a.w, h3, l3);
    const size_t o = (size_t)n * CIN + D1_ + lane * 4;
    *(uint2*)(g_x1h + o) = make_uint2(h0 | (h1 << 16), h2 | (h3 << 16));
    *(uint2*)(g_x1l + o) = make_uint2(l0 | (l1 << 16), l2 | (l3 << 16));
}

// ---------------------------------------------------------------------------
// Warp-MMA GEMM, fp16 2-term: C = (Xh + Xl) * Wh^T, f32 accum.
// CTA 128(M) x 64(N), 256 threads (4Mx2N warps), K-chunk 64, double-buffered
// 80KB smem, __launch_bounds__(256,2). Grid (4,512): 4 CTAs share X via L2.
// Buffer: Xh 16K | Xl 16K | Wh 8K = 40KB.
// ---------------------------------------------------------------------------
#define BUFSZ 40960
#define MMA_SMEM (2 * BUFSZ + 1024)

template <int LAYER>
__global__ void __launch_bounds__(256, 2) k_mma() {
    constexpr int K  = (LAYER == 1) ? CIN : CO;
    constexpr int KT = K / 64;
    const __half* xh = (LAYER == 1) ? g_x1h : g_x2h;
    const __half* xl = (LAYER == 1) ? g_x1l : g_x2l;
    const __half* wp = (LAYER == 1) ? g_w1 : g_w2;
    float* C = g_y1;

    extern __shared__ uint8_t dsm[];
    const uint32_t sbase = (smem_u32(dsm) + 1023) & ~1023u;

    const int tid  = threadIdx.x, wid = tid >> 5, lane = tid & 31;
    const int m0   = blockIdx.y << 7;     // sample tile (slow axis)
    const int n0   = blockIdx.x << 6;     // channel tile (fast axis, 4 share X)
    const int wm   = wid & 3, wn = wid >> 2;

    auto stage = [&](int kt) {
        const uint32_t base = sbase + (kt & 1) * BUFSZ;
        const int k0 = kt * 64;
        // X h+l: 2048 segs of 16B
#pragma unroll
        for (int i = 0; i < 8; i++) {
            const int q = tid + i * 256;
            const int sel = q >> 10;              // 0 xh, 1 xl
            const int r = (q & 1023) >> 3, c = q & 7;
            const __half* src = ((sel == 0) ? xh : xl) + (size_t)(m0 + r) * K + k0 + c * 8;
            const uint32_t dst = base + sel * 16384 + r * 128 + (((uint32_t)(c ^ (r & 7))) << 4);
            asm volatile("cp.async.cg.shared.global [%0], [%1], 16;" :: "r"(dst), "l"(src));
        }
        // W: 64 rows -> 512 segs of 16B
#pragma unroll
        for (int i = 0; i < 2; i++) {
            const int q = tid + i * 256;
            const int r = q >> 3, c = q & 7;
            const __half* src = wp + (size_t)(n0 + r) * K + k0 + c * 8;
            const uint32_t dst = base + 32768 + r * 128 + (((uint32_t)(c ^ (r & 7))) << 4);
            asm volatile("cp.async.cg.shared.global [%0], [%1], 16;" :: "r"(dst), "l"(src));
        }
        asm volatile("cp.async.commit_group;");
    };

    int rA[2], cAx = lane >> 4;
#pragma unroll
    for (int s = 0; s < 2; s++)
        rA[s] = wm * 32 + s * 16 + (lane & 7) + ((lane >> 3) & 1) * 8;
    int rB[2], cBx = (lane >> 3) & 1;
#pragma unroll
    for (int jj = 0; jj < 2; jj++)
        rB[jj] = wn * 32 + (jj * 2 + (lane >> 4)) * 8 + (lane & 7);

    float acc[2][4][4];
#pragma unroll
    for (int s = 0; s < 2; s++)
#pragma unroll
        for (int j = 0; j < 4; j++)
#pragma unroll
            for (int v = 0; v < 4; v++) acc[s][j][v] = 0.f;

    stage(0);
#pragma unroll 1
    for (int kt = 0; kt < KT; kt++) {
        if (kt + 1 < KT) { stage(kt + 1); asm volatile("cp.async.wait_group 1;"); }
        else             { asm volatile("cp.async.wait_group 0;"); }
        __syncthreads();
        const uint32_t base = sbase + (kt & 1) * BUFSZ;
        const uint32_t bXh = base, bXl = base + 16384, bW = base + 32768;
#pragma unroll
        for (int ks = 0; ks < 4; ks++) {
            uint32_t ah[2][4], al[2][4], bw[2][4];
#pragma unroll
            for (int s = 0; s < 2; s++) {
                const uint32_t off = rA[s] * 128 + (((uint32_t)((ks * 2 + cAx) ^ (rA[s] & 7))) << 4);
                asm volatile("ldmatrix.sync.aligned.m8n8.x4.shared.b16 {%0,%1,%2,%3}, [%4];"
                    : "=r"(ah[s][0]), "=r"(ah[s][1]), "=r"(ah[s][2]), "=r"(ah[s][3]) : "r"(bXh + off));
                asm volatile("ldmatrix.sync.aligned.m8n8.x4.shared.b16 {%0,%1,%2,%3}, [%4];"
                    : "=r"(al[s][0]), "=r"(al[s][1]), "=r"(al[s][2]), "=r"(al[s][3]) : "r"(bXl + off));
            }
#pragma unroll
            for (int jj = 0; jj < 2; jj++) {
                const uint32_t off = rB[jj] * 128 + (((uint32_t)((ks * 2 + cBx) ^ (rB[jj] & 7))) << 4);
                asm volatile("ldmatrix.sync.aligned.m8n8.x4.shared.b16 {%0,%1,%2,%3}, [%4];"
                    : "=r"(bw[jj][0]), "=r"(bw[jj][1]), "=r"(bw[jj][2]), "=r"(bw[jj][3]) : "r"(bW + off));
            }
#define MMA_(A, Bf, CC) asm volatile( \
    "mma.sync.aligned.m16n8k16.row.col.f32.f16.f16.f32 " \
    "{%0,%1,%2,%3}, {%4,%5,%6,%7}, {%8,%9}, {%0,%1,%2,%3};" \
    : "+f"((CC)[0]), "+f"((CC)[1]), "+f"((CC)[2]), "+f"((CC)[3]) \
    : "r"((A)[0]), "r"((A)[1]), "r"((A)[2]), "r"((A)[3]), "r"((Bf)[0]), "r"((Bf)[1]))
            // term-major: 8 independent accumulators per sweep
#pragma unroll
            for (int s = 0; s < 2; s++)
#pragma unroll
                for (int j = 0; j < 4; j++)
                    MMA_(ah[s], (&bw[j >> 1][(j & 1) * 2]), acc[s][j]);
#pragma unroll
            for (int s = 0; s < 2; s++)
#pragma unroll
                for (int j = 0; j < 4; j++)
                    MMA_(al[s], (&bw[j >> 1][(j & 1) * 2]), acc[s][j]);
#undef MMA_
        }
        __syncthreads();
    }

    // ---- lean epilogue: direct fp32 stores to C[n,256] ----
#pragma unroll
    for (int s = 0; s < 2; s++) {
        const int m = m0 + wm * 32 + s * 16 + (lane >> 2);
#pragma unroll
        for (int j = 0; j < 4; j++) {
            const int n = n0 + wn * 32 + j * 8 + (lane & 3) * 2;
            *(float2*)(C + (size_t)m * CO + n)       = make_float2(acc[s][j][0], acc[s][j][1]);
            *(float2*)(C + (size_t)(m + 8) * CO + n) = make_float2(acc[s][j][2], acc[s][j][3]);
        }
    }
}

// ---------------------------------------------------------------------------
// k_stats: per-channel partials over y [n,256]; deterministic.
// ---------------------------------------------------------------------------
__global__ void __launch_bounds__(256) k_stats() {
    __shared__ float4 ss[256], qq[256];
    const int j = blockIdx.x, t = threadIdx.x;
    const int cq = t & 63, rq = t >> 6;
    const float4* y = (const float4*)g_y1;
    float4 s = make_float4(0, 0, 0, 0), q = make_float4(0, 0, 0, 0);
    for (int i = 0; i < 64; i++) {
        const int row = j * 256 + rq * 64 + i;
        const float4 v = y[(size_t)row * 64 + cq];
        s.x += v.x; s.y += v.y; s.z += v.z; s.w += v.w;
        q.x = fmaf(v.x, v.x, q.x); q.y = fmaf(v.y, v.y, q.y);
        q.z = fmaf(v.z, v.z, q.z); q.w = fmaf(v.w, v.w, q.w);
    }
    ss[t] = s; qq[t] = q;
    __syncthreads();
    if (t < 64) {
        float4 a = ss[t], b = ss[t + 64], c = ss[t + 128], d = ss[t + 192];
        float4 e = qq[t], f = qq[t + 64], g = qq[t + 128], h = qq[t + 192];
        float4 so = make_float4((a.x + b.x) + (c.x + d.x), (a.y + b.y) + (c.y + d.y),
                                (a.z + b.z) + (c.z + d.z), (a.w + b.w) + (c.w + d.w));
        float4 qo = make_float4((e.x + f.x) + (g.x + h.x), (e.y + f.y) + (g.y + h.y),
                                (e.z + f.z) + (g.z + h.z), (e.w + f.w) + (g.w + h.w));
        *(float4*)&g_psum[j * 256 + t * 4] = so;
        *(float4*)&g_psq[j * 256 + t * 4]  = qo;
    }
}

// ---------------------------------------------------------------------------
// fold: reduce 256 partials/channel -> folded BN affine
// ---------------------------------------------------------------------------
__global__ void k_fold(const float* __restrict__ gamma, const float* __restrict__ beta,
                       int layer) {
    const int c = threadIdx.x;
    float s = 0.f, q = 0.f;
    for (int j = 0; j < 256; j++) {
        s += g_psum[j * 256 + c];
        q += g_psq[j * 256 + c];
    }
    const float mean = s * (1.f / (float)NS);
    const float var  = q * (1.f / (float)NS) - mean * mean;
    const float a = gamma[c] * rsqrtf(var + 1e-5f);
    const float b = beta[c] - mean * a;
    if (layer == 1) { g_a1[c] = a; g_b1[c] = b; }
    else            { g_a2[c] = a; g_b2[c] = b; }
}

// ---------------------------------------------------------------------------
// x2 = split_f16(relu(a1*y1 + b1))
// ---------------------------------------------------------------------------
__global__ void __launch_bounds__(256) k_x2() {
    const size_t i = (size_t)blockIdx.x * 256 + threadIdx.x;
    const size_t row = i >> 6;
    const int cq = (int)(i & 63), c0 = cq * 4;
    float4 v = ((const float4*)g_y1)[row * 64 + cq];
    const float4 a = *(const float4*)&g_a1[c0];
    const float4 b = *(const float4*)&g_b1[c0];
    v.x = fmaxf(fmaf(a.x, v.x, b.x), 0.f);
    v.y = fmaxf(fmaf(a.y, v.y, b.y), 0.f);
    v.z = fmaxf(fmaf(a.z, v.z, b.z), 0.f);
    v.w = fmaxf(fmaf(a.w, v.w, b.w), 0.f);
    uint32_t h0, l0, h1, l1, h2, l2, h3, l3;
    split_f16(v.x, h0, l0); split_f16(v.y, h1, l1);
    split_f16(v.z, h2, l2); split_f16(v.w, h3, l3);
    const size_t o = row * CO + c0;
    *(uint2*)(g_x2h + o) = make_uint2(h0 | (h1 << 16), h2 | (h3 << 16));
    *(uint2*)(g_x2l + o) = make_uint2(l0 | (l1 << 16), l2 | (l3 << 16));
}

// ---------------------------------------------------------------------------
// finalize: out[b,o,n] = relu(a2*y2[n,o] + b2)
// ---------------------------------------------------------------------------
__global__ void k_finalize(float* __restrict__ out) {
    __shared__ float t[32][33];
    const int b = blockIdx.z, o0 = blockIdx.y * 32, n0 = blockIdx.x * 32;
    const int tx = threadIdx.x, ty = threadIdx.y;
    const float a = g_a2[o0 + tx], bb = g_b2[o0 + tx];
#pragma unroll
    for (int i = 0; i < 4; i++) {
        const int n = n0 + ty + i * 8;
        const float v = g_y1[(size_t)(b * NPT + n) * CO + o0 + tx];
        t[tx][ty + i * 8] = fmaxf(fmaf(a, v, bb), 0.f);
    }
    __syncthreads();
#pragma unroll
    for (int i = 0; i < 4; i++)
        out[((size_t)b * CO + o0 + ty + i * 8) * NPT + n0 + tx] = t[ty + i * 8][tx];
}

// ---------------------------------------------------------------------------
// Launch
// ---------------------------------------------------------------------------
extern "C" void kernel_launch(void* const* d_in, const int* in_sizes, int n_in,
                              void* d_out, int out_size) {
    const float* xyz1    = (const float*)d_in[0];
    const float* xyz2    = (const float*)d_in[1];
    const float* points1 = (const float*)d_in[2];
    const float* points2 = (const float*)d_in[3];
    const float* W1      = (const float*)d_in[4];
    const float* g1      = (const float*)d_in[6];
    const float* be1     = (const float*)d_in[7];
    const float* W2      = (const float*)d_in[8];
    const float* g2      = (const float*)d_in[10];
    const float* be2     = (const float*)d_in[11];
    float* out = (float*)d_out;

    cudaFuncSetAttribute(k_mma<1>, cudaFuncAttributeMaxDynamicSharedMemorySize, MMA_SMEM);
    cudaFuncSetAttribute(k_mma<2>, cudaFuncAttributeMaxDynamicSharedMemorySize, MMA_SMEM);

    k_prep<<<19072, 256>>>(W1, W2, points2, points1);
    k_nn<<<dim3(32, 16), 256>>>(xyz1, xyz2);
    k_gather<<<8192, 256>>>();
    k_mma<1><<<dim3(4, 512), 256, MMA_SMEM>>>();
    k_stats<<<256, 256>>>();
    k_fold<<<1, 256>>>(g1, be1, 1);
    k_x2<<<16384, 256>>>();
    k_mma<2><<<dim3(4, 512), 256, MMA_SMEM>>>();
    k_stats<<<256, 256>>>();
    k_fold<<<1, 256>>>(g2, be2, 2);
    k_finalize<<<dim3(128, 8, 16), dim3(32, 8)>>>(out);
}

// round 16
// speedup vs baseline: 1.3288x; 1.0479x over previous
#include <cuda_runtime.h>
#include <cuda_fp16.h>
#include <cstdint>
#include <cstddef>

#define B_   16
#define NPT  4096
#define SPT  1024
#define D1_  256
#define D2_  128
#define CIN  384
#define CO   256
#define NS   (B_*NPT)   // 65536

// ---------------------------------------------------------------------------
// Scratch (fp16 operands: X split hi/lo, W single-term)
// ---------------------------------------------------------------------------
__device__ float  g_p2t[B_ * SPT * D2_];
__device__ __half g_x1h[(size_t)NS * CIN];
__device__ __half g_x1l[(size_t)NS * CIN];
__device__ __half g_x2h[(size_t)NS * CO];
__device__ __half g_x2l[(size_t)NS * CO];
__device__ float  g_y1[(size_t)NS * CO];            // y1, then reused as y2
__device__ __half g_w1[CO * CIN];
__device__ __half g_w2[CO * CO];
__device__ float g_psum[256 * 256], g_psq[256 * 256]; // [rowblock][channel]
__device__ float g_a1[CO], g_b1[CO], g_a2[CO], g_b2[CO];
__device__ float4 g_nnw4[NS];
__device__ int4   g_nni4[NS];

__device__ __forceinline__ uint32_t smem_u32(const void* p) {
    uint32_t a;
    asm("{ .reg .u64 t; cvta.to.shared.u64 t, %1; cvt.u32.u64 %0, t; }" : "=r"(a) : "l"(p));
    return a;
}
__device__ __forceinline__ void split_f16(float a, uint32_t& h, uint32_t& l) {
    __half hb = __float2half_rn(a);
    __half lb = __float2half_rn(a - __half2float(hb));
    h = (uint32_t)__half_as_ushort(hb);
    l = (uint32_t)__half_as_ushort(lb);
}

// ---------------------------------------------------------------------------
// k_prep: fused W-convert + points2 transpose + points1 transpose/split.
// blockIdx.x: [0,640) W convert | [640,2688) tp2 | [2688,19072) tp1
// ---------------------------------------------------------------------------
__global__ void __launch_bounds__(256) k_prep(const float* __restrict__ W1,
                                              const float* __restrict__ W2,
                                              const float* __restrict__ p2,
                                              const float* __restrict__ p1) {
    __shared__ float t[32][33];
    const int bi = blockIdx.x, tid = threadIdx.x;
    const int tx = tid & 31, ty = tid >> 5;

    if (bi < 640) {                       // ---- W convert (single fp16 term) ----
        const int i = bi * 256 + tid;
        if (i < CO * CIN) g_w1[i] = __float2half_rn(W1[i]);
        else              g_w2[i - CO * CIN] = __float2half_rn(W2[i - CO * CIN]);
        return;
    }
    if (bi < 2688) {                      // ---- tp2: [B,D2,S] -> [B,S,D2] ----
        const int idx = bi - 640;
        const int b = idx >> 7, rem = idx & 127;
        const int c0 = (rem >> 5) * 32, s0 = (rem & 31) * 32;
#pragma unroll
        for (int i = 0; i < 4; i++)
            t[ty + i * 8][tx] = p2[((size_t)b * D2_ + c0 + ty + i * 8) * SPT + s0 + tx];
        __syncthreads();
#pragma unroll
        for (int i = 0; i < 4; i++)
            g_p2t[((size_t)b * SPT + s0 + ty + i * 8) * D2_ + c0 + tx] = t[tx][ty + i * 8];
        return;
    }
    {                                     // ---- tp1: X1 cols [0,256) fp16 hi/lo ----
        const int idx = bi - 2688;
        const int b = idx >> 10, rem = idx & 1023;
        const int c0 = (rem >> 7) * 32, n0 = (rem & 127) * 32;
#pragma unroll
        for (int i = 0; i < 4; i++)
            t[ty + i * 8][tx] = p1[((size_t)b * D1_ + c0 + ty + i * 8) * NPT + n0 + tx];
        __syncthreads();
#pragma unroll
        for (int w = 0; w < 2; w++) {
            const int v = w * 256 + tid;
            const int n = v >> 4, u = v & 15;
            uint32_t h0, l0, h1, l1;
            split_f16(t[2 * u][n], h0, l0);
            split_f16(t[2 * u + 1][n], h1, l1);
            const size_t a = (size_t)(b * NPT + n0 + n) * CIN + c0 + 2 * u;
            *(uint32_t*)(g_x1h + a) = h0 | (h1 << 16);
            *(uint32_t*)(g_x1l + a) = l0 | (l1 << 16);
        }
    }
}

// ---------------------------------------------------------------------------
// k_nn: split-S 3-NN (2 threads/query, rare-branch insertion, smem merge).
// ---------------------------------------------------------------------------
__global__ void __launch_bounds__(256) k_nn(const float* __restrict__ xyz1,
                                            const float* __restrict__ xyz2) {
    __shared__ float4 s2[SPT];
    __shared__ float sd[3][128];
    __shared__ int   si[3][128];
    const int b = blockIdx.y, tid = threadIdx.x;
    const int q = tid & 127, half = tid >> 7;
    const int n = blockIdx.x * 128 + q;
    for (int i = tid; i < SPT; i += 256) {
        const float x = xyz2[(size_t)b * 3072 + i];
        const float y = xyz2[(size_t)b * 3072 + 1024 + i];
        const float z = xyz2[(size_t)b * 3072 + 2048 + i];
        s2[i] = make_float4(x, y, z, fmaf(x, x, fmaf(y, y, z * z)));
    }
    __syncthreads();

    const float px = xyz1[((size_t)b * 3 + 0) * NPT + n];
    const float py = xyz1[((size_t)b * 3 + 1) * NPT + n];
    const float pz = xyz1[((size_t)b * 3 + 2) * NPT + n];
    const float mx = -2.f * px, my = -2.f * py, mz = -2.f * pz;
    const float a2 = fmaf(px, px, fmaf(py, py, pz * pz));

    float d0 = 1e30f, d1 = 1e30f, d2 = 1e30f;
    int   i0 = 0, i1 = 0, i2 = 0;
    const int sbeg = half << 9;
#pragma unroll 4
    for (int s = sbeg; s < sbeg + 512; s++) {
        const float4 v = s2[s];
        const float d = fmaf(mx, v.x, fmaf(my, v.y, fmaf(mz, v.z, v.w)));
        if (d < d2) {
            const bool p0 = d < d0, p1 = d < d1;
            i2 = p1 ? i1 : s;
            d2 = p1 ? d1 : d;
            i1 = p0 ? i0 : (p1 ? s : i1);
            d1 = p0 ? d0 : (p1 ? d : d1);
            i0 = p0 ? s : i0;
            d0 = p0 ? d : d0;
        }
    }
    if (half) {
        sd[0][q] = d0; sd[1][q] = d1; sd[2][q] = d2;
        si[0][q] = i0; si[1][q] = i1; si[2][q] = i2;
    }
    __syncthreads();
    if (!half) {
        float b0 = sd[0][q], b1 = sd[1][q], b2 = sd[2][q];
        int   j0 = si[0][q], j1 = si[1][q], j2 = si[2][q];
        float m0, m1, m2; int o0, o1, o2;
        bool t = b0 < d0;                       // ties -> lower-index half (d)
        m0 = t ? b0 : d0; o0 = t ? j0 : i0;
        if (t) { b0 = b1; j0 = j1; b1 = b2; j1 = j2; }
        else   { d0 = d1; i0 = i1; d1 = d2; i1 = i2; }
        t = b0 < d0;
        m1 = t ? b0 : d0; o1 = t ? j0 : i0;
        if (t) { b0 = b1; j0 = j1; }
        else   { d0 = d1; i0 = i1; }
        t = b0 < d0;
        m2 = t ? b0 : d0; o2 = t ? j0 : i0;

        const float f0 = sqrtf(fmaxf(m0 + a2, 0.f));
        const float f1 = sqrtf(fmaxf(m1 + a2, 0.f));
        const float f2 = sqrtf(fmaxf(m2 + a2, 0.f));
        float w0 = 1.f / (f0 + 1e-10f);
        float w1 = 1.f / (f1 + 1e-10f);
        float w2 = 1.f / (f2 + 1e-10f);
        const float inv = 1.f / (w0 + w1 + w2);
        const int g = b * NPT + n;
        g_nnw4[g] = make_float4(w0 * inv, w1 * inv, w2 * inv, 0.f);
        g_nni4[g] = make_int4(o0, o1, o2, 0);
    }
}

// ---------------------------------------------------------------------------
// k_gather: warp per query; register accumulation; fp16 hi/lo out.
// ---------------------------------------------------------------------------
__global__ void __launch_bounds__(256) k_gather() {
    const int wid = threadIdx.x >> 5, lane = threadIdx.x & 31;
    const int n = blockIdx.x * 8 + wid;
    const int b = n >> 12;
    const float4 wv = g_nnw4[n];
    const int4   iv = g_nni4[n];
    const float* p2t = g_p2t + (size_t)b * SPT * D2_;
    const float4 v0 = *(const float4*)(p2t + (size_t)iv.x * D2_ + lane * 4);
    const float4 v1 = *(const float4*)(p2t + (size_t)iv.y * D2_ + lane * 4);
    const float4 v2 = *(const float4*)(p2t + (size_t)iv.z * D2_ + lane * 4);
    float4 a;
    a.x = fmaf(wv.x, v0.x, fmaf(wv.y, v1.x, wv.z * v2.x));
    a.y = fmaf(wv.x, v0.y, fmaf(wv.y, v1.y, wv.z * v2.y));
    a.z = fmaf(wv.x, v0.z, fmaf(wv.y, v1.z, wv.z * v2.z));
    a.w = fmaf(wv.x, v0.w, fmaf(wv.y, v1.w, wv.z * v2.w));
    uint32_t h0, l0, h1, l1, h2, l2, h3, l3;
    split_f16(a.x, h0, l0); split_f16(a.y, h1, l1);
    split_f16(a.z, h2, l2); split_f16(a.w, h3, l3);
    const size_t o = (size_t)n * CIN + D1_ + lane * 4;
    *(uint2*)(g_x1h + o) = make_uint2(h0 | (h1 << 16), h2 | (h3 << 16));
    *(uint2*)(g_x1l + o) = make_uint2(l0 | (l1 << 16), l2 | (l3 << 16));
}

// ---------------------------------------------------------------------------
// Warp-MMA GEMM, fp16 2-term: C = (Xh + Xl) * W^T, f32 accum.
// CTA 128(M) x 128(N), 256 threads (4Mx2N warps, warp 32x64), K-chunk 64,
// double-buffered 96KB smem, __launch_bounds__(256,2) -> 2 CTAs/SM.
// Grid (2, 512): the 2 CTAs sharing an X tile are adjacent -> X L2 reuse.
// Buffer: Xh 16K | Xl 16K | W 16K = 48KB.
// ---------------------------------------------------------------------------
#define BUFSZ 49152
#define MMA_SMEM (2 * BUFSZ + 1024)

template <int LAYER>
__global__ void __launch_bounds__(256, 2) k_mma() {
    constexpr int K  = (LAYER == 1) ? CIN : CO;
    constexpr int KT = K / 64;
    const __half* xh = (LAYER == 1) ? g_x1h : g_x2h;
    const __half* xl = (LAYER == 1) ? g_x1l : g_x2l;
    const __half* wp = (LAYER == 1) ? g_w1 : g_w2;
    float* C = g_y1;

    extern __shared__ uint8_t dsm[];
    const uint32_t sbase = (smem_u32(dsm) + 1023) & ~1023u;

    const int tid  = threadIdx.x, wid = tid >> 5, lane = tid & 31;
    const int m0   = blockIdx.y << 7;     // sample tile (slow axis)
    const int n0   = blockIdx.x << 7;     // channel tile (fast axis, pair shares X)
    const int wm   = wid & 3, wn = wid >> 2;

    auto stage = [&](int kt) {
        const uint32_t base = sbase + (kt & 1) * BUFSZ;
        const int k0 = kt * 64;
        // X h+l: 2048 segs of 16B
#pragma unroll
        for (int i = 0; i < 8; i++) {
            const int q = tid + i * 256;
            const int sel = q >> 10;              // 0 xh, 1 xl
            const int r = (q & 1023) >> 3, c = q & 7;
            const __half* src = ((sel == 0) ? xh : xl) + (size_t)(m0 + r) * K + k0 + c * 8;
            const uint32_t dst = base + sel * 16384 + r * 128 + (((uint32_t)(c ^ (r & 7))) << 4);
            asm volatile("cp.async.cg.shared.global [%0], [%1], 16;" :: "r"(dst), "l"(src));
        }
        // W: 128 rows -> 1024 segs of 16B
#pragma unroll
        for (int i = 0; i < 4; i++) {
            const int q = tid + i * 256;
            const int r = q >> 3, c = q & 7;
            const __half* src = wp + (size_t)(n0 + r) * K + k0 + c * 8;
            const uint32_t dst = base + 32768 + r * 128 + (((uint32_t)(c ^ (r & 7))) << 4);
            asm volatile("cp.async.cg.shared.global [%0], [%1], 16;" :: "r"(dst), "l"(src));
        }
        asm volatile("cp.async.commit_group;");
    };

    int rA[2], cAx = lane >> 4;
#pragma unroll
    for (int s = 0; s < 2; s++)
        rA[s] = wm * 32 + s * 16 + (lane & 7) + ((lane >> 3) & 1) * 8;
    int rB[4], cBx = (lane >> 3) & 1;
#pragma unroll
    for (int jj = 0; jj < 4; jj++)
        rB[jj] = wn * 64 + (jj * 2 + (lane >> 4)) * 8 + (lane & 7);

    float acc[2][8][4];
#pragma unroll
    for (int s = 0; s < 2; s++)
#pragma unroll
        for (int j = 0; j < 8; j++)
#pragma unroll
            for (int v = 0; v < 4; v++) acc[s][j][v] = 0.f;

    stage(0);
#pragma unroll 1
    for (int kt = 0; kt < KT; kt++) {
        if (kt + 1 < KT) { stage(kt + 1); asm volatile("cp.async.wait_group 1;"); }
        else             { asm volatile("cp.async.wait_group 0;"); }
        __syncthreads();
        const uint32_t base = sbase + (kt & 1) * BUFSZ;
        const uint32_t bXh = base, bXl = base + 16384, bW = base + 32768;
#pragma unroll
        for (int ks = 0; ks < 4; ks++) {
            uint32_t ah[2][4], al[2][4], bw[4][4];
#pragma unroll
            for (int s = 0; s < 2; s++) {
                const uint32_t off = rA[s] * 128 + (((uint32_t)((ks * 2 + cAx) ^ (rA[s] & 7))) << 4);
                asm volatile("ldmatrix.sync.aligned.m8n8.x4.shared.b16 {%0,%1,%2,%3}, [%4];"
                    : "=r"(ah[s][0]), "=r"(ah[s][1]), "=r"(ah[s][2]), "=r"(ah[s][3]) : "r"(bXh + off));
                asm volatile("ldmatrix.sync.aligned.m8n8.x4.shared.b16 {%0,%1,%2,%3}, [%4];"
                    : "=r"(al[s][0]), "=r"(al[s][1]), "=r"(al[s][2]), "=r"(al[s][3]) : "r"(bXl + off));
            }
#pragma unroll
            for (int jj = 0; jj < 4; jj++) {
                const uint32_t off = rB[jj] * 128 + (((uint32_t)((ks * 2 + cBx) ^ (rB[jj] & 7))) << 4);
                asm volatile("ldmatrix.sync.aligned.m8n8.x4.shared.b16 {%0,%1,%2,%3}, [%4];"
                    : "=r"(bw[jj][0]), "=r"(bw[jj][1]), "=r"(bw[jj][2]), "=r"(bw[jj][3]) : "r"(bW + off));
            }
#define MMA_(A, Bf, CC) asm volatile( \
    "mma.sync.aligned.m16n8k16.row.col.f32.f16.f16.f32 " \
    "{%0,%1,%2,%3}, {%4,%5,%6,%7}, {%8,%9}, {%0,%1,%2,%3};" \
    : "+f"((CC)[0]), "+f"((CC)[1]), "+f"((CC)[2]), "+f"((CC)[3]) \
    : "r"((A)[0]), "r"((A)[1]), "r"((A)[2]), "r"((A)[3]), "r"((Bf)[0]), "r"((Bf)[1]))
            // term-major: 16 independent accumulators per sweep
#pragma unroll
            for (int s = 0; s < 2; s++)
#pragma unroll
                for (int j = 0; j < 8; j++)
                    MMA_(ah[s], (&bw[j >> 1][(j & 1) * 2]), acc[s][j]);
#pragma unroll
            for (int s = 0; s < 2; s++)
#pragma unroll
                for (int j = 0; j < 8; j++)
                    MMA_(al[s], (&bw[j >> 1][(j & 1) * 2]), acc[s][j]);
#undef MMA_
        }
        __syncthreads();
    }

    // ---- lean epilogue: direct fp32 stores to C[n,256] ----
#pragma unroll
    for (int s = 0; s < 2; s++) {
        const int m = m0 + wm * 32 + s * 16 + (lane >> 2);
#pragma unroll
        for (int j = 0; j < 8; j++) {
            const int n = n0 + wn * 64 + j * 8 + (lane & 3) * 2;
            *(float2*)(C + (size_t)m * CO + n)       = make_float2(acc[s][j][0], acc[s][j][1]);
            *(float2*)(C + (size_t)(m + 8) * CO + n) = make_float2(acc[s][j][2], acc[s][j][3]);
        }
    }
}

// ---------------------------------------------------------------------------
// k_stats: per-channel partials over y [n,256]; deterministic.
// ---------------------------------------------------------------------------
__global__ void __launch_bounds__(256) k_stats() {
    __shared__ float4 ss[256], qq[256];
    const int j = blockIdx.x, t = threadIdx.x;
    const int cq = t & 63, rq = t >> 6;
    const float4* y = (const float4*)g_y1;
    float4 s = make_float4(0, 0, 0, 0), q = make_float4(0, 0, 0, 0);
    for (int i = 0; i < 64; i++) {
        const int row = j * 256 + rq * 64 + i;
        const float4 v = y[(size_t)row * 64 + cq];
        s.x += v.x; s.y += v.y; s.z += v.z; s.w += v.w;
        q.x = fmaf(v.x, v.x, q.x); q.y = fmaf(v.y, v.y, q.y);
        q.z = fmaf(v.z, v.z, q.z); q.w = fmaf(v.w, v.w, q.w);
    }
    ss[t] = s; qq[t] = q;
    __syncthreads();
    if (t < 64) {
        float4 a = ss[t], b = ss[t + 64], c = ss[t + 128], d = ss[t + 192];
        float4 e = qq[t], f = qq[t + 64], g = qq[t + 128], h = qq[t + 192];
        float4 so = make_float4((a.x + b.x) + (c.x + d.x), (a.y + b.y) + (c.y + d.y),
                                (a.z + b.z) + (c.z + d.z), (a.w + b.w) + (c.w + d.w));
        float4 qo = make_float4((e.x + f.x) + (g.x + h.x), (e.y + f.y) + (g.y + h.y),
                                (e.z + f.z) + (g.z + h.z), (e.w + f.w) + (g.w + h.w));
        *(float4*)&g_psum[j * 256 + t * 4] = so;
        *(float4*)&g_psq[j * 256 + t * 4]  = qo;
    }
}

// ---------------------------------------------------------------------------
// fold: reduce 256 partials/channel -> folded BN affine
// ---------------------------------------------------------------------------
__global__ void k_fold(const float* __restrict__ gamma, const float* __restrict__ beta,
                       int layer) {
    const int c = threadIdx.x;
    float s = 0.f, q = 0.f;
    for (int j = 0; j < 256; j++) {
        s += g_psum[j * 256 + c];
        q += g_psq[j * 256 + c];
    }
    const float mean = s * (1.f / (float)NS);
    const float var  = q * (1.f / (float)NS) - mean * mean;
    const float a = gamma[c] * rsqrtf(var + 1e-5f);
    const float b = beta[c] - mean * a;
    if (layer == 1) { g_a1[c] = a; g_b1[c] = b; }
    else            { g_a2[c] = a; g_b2[c] = b; }
}

// ---------------------------------------------------------------------------
// x2 = split_f16(relu(a1*y1 + b1))
// ---------------------------------------------------------------------------
__global__ void __launch_bounds__(256) k_x2() {
    const size_t i = (size_t)blockIdx.x * 256 + threadIdx.x;
    const size_t row = i >> 6;
    const int cq = (int)(i & 63), c0 = cq * 4;
    float4 v = ((const float4*)g_y1)[row * 64 + cq];
    const float4 a = *(const float4*)&g_a1[c0];
    const float4 b = *(const float4*)&g_b1[c0];
    v.x = fmaxf(fmaf(a.x, v.x, b.x), 0.f);
    v.y = fmaxf(fmaf(a.y, v.y, b.y), 0.f);
    v.z = fmaxf(fmaf(a.z, v.z, b.z), 0.f);
    v.w = fmaxf(fmaf(a.w, v.w, b.w), 0.f);
    uint32_t h0, l0, h1, l1, h2, l2, h3, l3;
    split_f16(v.x, h0, l0); split_f16(v.y, h1, l1);
    split_f16(v.z, h2, l2); split_f16(v.w, h3, l3);
    const size_t o = row * CO + c0;
    *(uint2*)(g_x2h + o) = make_uint2(h0 | (h1 << 16), h2 | (h3 << 16));
    *(uint2*)(g_x2l + o) = make_uint2(l0 | (l1 << 16), l2 | (l3 << 16));
}

// ---------------------------------------------------------------------------
// finalize: out[b,o,n] = relu(a2*y2[n,o] + b2)
// ---------------------------------------------------------------------------
__global__ void k_finalize(float* __restrict__ out) {
    __shared__ float t[32][33];
    const int b = blockIdx.z, o0 = blockIdx.y * 32, n0 = blockIdx.x * 32;
    const int tx = threadIdx.x, ty = threadIdx.y;
    const float a = g_a2[o0 + tx], bb = g_b2[o0 + tx];
#pragma unroll
    for (int i = 0; i < 4; i++) {
        const int n = n0 + ty + i * 8;
        const float v = g_y1[(size_t)(b * NPT + n) * CO + o0 + tx];
        t[tx][ty + i * 8] = fmaxf(fmaf(a, v, bb), 0.f);
    }
    __syncthreads();
#pragma unroll
    for (int i = 0; i < 4; i++)
        out[((size_t)b * CO + o0 + ty + i * 8) * NPT + n0 + tx] = t[ty + i * 8][tx];
}

// ---------------------------------------------------------------------------
// Launch
// ---------------------------------------------------------------------------
extern "C" void kernel_launch(void* const* d_in, const int* in_sizes, int n_in,
                              void* d_out, int out_size) {
    const float* xyz1    = (const float*)d_in[0];
    const float* xyz2    = (const float*)d_in[1];
    const float* points1 = (const float*)d_in[2];
    const float* points2 = (const float*)d_in[3];
    const float* W1      = (const float*)d_in[4];
    const float* g1      = (const float*)d_in[6];
    const float* be1     = (const float*)d_in[7];
    const float* W2      = (const float*)d_in[8];
    const float* g2      = (const float*)d_in[10];
    const float* be2     = (const float*)d_in[11];
    float* out = (float*)d_out;

    cudaFuncSetAttribute(k_mma<1>, cudaFuncAttributeMaxDynamicSharedMemorySize, MMA_SMEM);
    cudaFuncSetAttribute(k_mma<2>, cudaFuncAttributeMaxDynamicSharedMemorySize, MMA_SMEM);

    k_prep<<<19072, 256>>>(W1, W2, points2, points1);
    k_nn<<<dim3(32, 16), 256>>>(xyz1, xyz2);
    k_gather<<<8192, 256>>>();
    k_mma<1><<<dim3(2, 512), 256, MMA_SMEM>>>();
    k_stats<<<256, 256>>>();
    k_fold<<<1, 256>>>(g1, be1, 1);
    k_x2<<<16384, 256>>>();
    k_mma<2><<<dim3(2, 512), 256, MMA_SMEM>>>();
    k_stats<<<256, 256>>>();
    k_fold<<<1, 256>>>(g2, be2, 2);
    k_finalize<<<dim3(128, 8, 16), dim3(32, 8)>>>(out);
}

// round 17
// speedup vs baseline: 1.4370x; 1.0815x over previous
#include <cuda_runtime.h>
#include <cuda_fp16.h>
#include <cstdint>
#include <cstddef>

#define B_   16
#define NPT  4096
#define SPT  1024
#define D1_  256
#define D2_  128
#define CIN  384
#define CO   256
#define NS   (B_*NPT)   // 65536

// ---------------------------------------------------------------------------
// Scratch (fp16 operands: X1 split hi/lo, X2 single, W single-term)
// ---------------------------------------------------------------------------
__device__ float  g_p2t[B_ * SPT * D2_];
__device__ __half g_x1h[(size_t)NS * CIN];
__device__ __half g_x1l[(size_t)NS * CIN];
__device__ __half g_x2h[(size_t)NS * CO];
__device__ float  g_y1[(size_t)NS * CO];            // y1, then reused as y2
__device__ __half g_w1[CO * CIN];
__device__ __half g_w2[CO * CO];
__device__ float g_psum[256 * 256], g_psq[256 * 256]; // [rowblock][channel]
__device__ float g_a1[CO], g_b1[CO], g_a2[CO], g_b2[CO];
__device__ float4 g_nnw4[NS];
__device__ int4   g_nni4[NS];

__device__ __forceinline__ uint32_t smem_u32(const void* p) {
    uint32_t a;
    asm("{ .reg .u64 t; cvta.to.shared.u64 t, %1; cvt.u32.u64 %0, t; }" : "=r"(a) : "l"(p));
    return a;
}
__device__ __forceinline__ void split_f16(float a, uint32_t& h, uint32_t& l) {
    __half hb = __float2half_rn(a);
    __half lb = __float2half_rn(a - __half2float(hb));
    h = (uint32_t)__half_as_ushort(hb);
    l = (uint32_t)__half_as_ushort(lb);
}

// ---------------------------------------------------------------------------
// k_prep: fused W-convert + points2 transpose + points1 transpose/split.
// blockIdx.x: [0,640) W convert | [640,2688) tp2 | [2688,19072) tp1
// ---------------------------------------------------------------------------
__global__ void __launch_bounds__(256) k_prep(const float* __restrict__ W1,
                                              const float* __restrict__ W2,
                                              const float* __restrict__ p2,
                                              const float* __restrict__ p1) {
    __shared__ float t[32][33];
    const int bi = blockIdx.x, tid = threadIdx.x;
    const int tx = tid & 31, ty = tid >> 5;

    if (bi < 640) {                       // ---- W convert ----
        const int i = bi * 256 + tid;
        if (i < CO * CIN) g_w1[i] = __float2half_rn(W1[i]);
        else              g_w2[i - CO * CIN] = __float2half_rn(W2[i - CO * CIN]);
        return;
    }
    if (bi < 2688) {                      // ---- tp2 ----
        const int idx = bi - 640;
        const int b = idx >> 7, rem = idx & 127;
        const int c0 = (rem >> 5) * 32, s0 = (rem & 31) * 32;
#pragma unroll
        for (int i = 0; i < 4; i++)
            t[ty + i * 8][tx] = p2[((size_t)b * D2_ + c0 + ty + i * 8) * SPT + s0 + tx];
        __syncthreads();
#pragma unroll
        for (int i = 0; i < 4; i++)
            g_p2t[((size_t)b * SPT + s0 + ty + i * 8) * D2_ + c0 + tx] = t[tx][ty + i * 8];
        return;
    }
    {                                     // ---- tp1: X1 cols [0,256) fp16 hi/lo ----
        const int idx = bi - 2688;
        const int b = idx >> 10, rem = idx & 1023;
        const int c0 = (rem >> 7) * 32, n0 = (rem & 127) * 32;
#pragma unroll
        for (int i = 0; i < 4; i++)
            t[ty + i * 8][tx] = p1[((size_t)b * D1_ + c0 + ty + i * 8) * NPT + n0 + tx];
        __syncthreads();
#pragma unroll
        for (int w = 0; w < 2; w++) {
            const int v = w * 256 + tid;
            const int n = v >> 4, u = v & 15;
            uint32_t h0, l0, h1, l1;
            split_f16(t[2 * u][n], h0, l0);
            split_f16(t[2 * u + 1][n], h1, l1);
            const size_t a = (size_t)(b * NPT + n0 + n) * CIN + c0 + 2 * u;
            *(uint32_t*)(g_x1h + a) = h0 | (h1 << 16);
            *(uint32_t*)(g_x1l + a) = l0 | (l1 << 16);
        }
    }
}

// ---------------------------------------------------------------------------
// k_nn: split-S 3-NN (2 threads/query, rare-branch insertion, smem merge).
// ---------------------------------------------------------------------------
__global__ void __launch_bounds__(256) k_nn(const float* __restrict__ xyz1,
                                            const float* __restrict__ xyz2) {
    __shared__ float4 s2[SPT];
    __shared__ float sd[3][128];
    __shared__ int   si[3][128];
    const int b = blockIdx.y, tid = threadIdx.x;
    const int q = tid & 127, half = tid >> 7;
    const int n = blockIdx.x * 128 + q;
    for (int i = tid; i < SPT; i += 256) {
        const float x = xyz2[(size_t)b * 3072 + i];
        const float y = xyz2[(size_t)b * 3072 + 1024 + i];
        const float z = xyz2[(size_t)b * 3072 + 2048 + i];
        s2[i] = make_float4(x, y, z, fmaf(x, x, fmaf(y, y, z * z)));
    }
    __syncthreads();

    const float px = xyz1[((size_t)b * 3 + 0) * NPT + n];
    const float py = xyz1[((size_t)b * 3 + 1) * NPT + n];
    const float pz = xyz1[((size_t)b * 3 + 2) * NPT + n];
    const float mx = -2.f * px, my = -2.f * py, mz = -2.f * pz;
    const float a2 = fmaf(px, px, fmaf(py, py, pz * pz));

    float d0 = 1e30f, d1 = 1e30f, d2 = 1e30f;
    int   i0 = 0, i1 = 0, i2 = 0;
    const int sbeg = half << 9;
#pragma unroll 4
    for (int s = sbeg; s < sbeg + 512; s++) {
        const float4 v = s2[s];
        const float d = fmaf(mx, v.x, fmaf(my, v.y, fmaf(mz, v.z, v.w)));
        if (d < d2) {
            const bool p0 = d < d0, p1 = d < d1;
            i2 = p1 ? i1 : s;
            d2 = p1 ? d1 : d;
            i1 = p0 ? i0 : (p1 ? s : i1);
            d1 = p0 ? d0 : (p1 ? d : d1);
            i0 = p0 ? s : i0;
            d0 = p0 ? d : d0;
        }
    }
    if (half) {
        sd[0][q] = d0; sd[1][q] = d1; sd[2][q] = d2;
        si[0][q] = i0; si[1][q] = i1; si[2][q] = i2;
    }
    __syncthreads();
    if (!half) {
        float b0 = sd[0][q], b1 = sd[1][q], b2 = sd[2][q];
        int   j0 = si[0][q], j1 = si[1][q], j2 = si[2][q];
        float m0, m1, m2; int o0, o1, o2;
        bool t = b0 < d0;                       // ties -> lower-index half (d)
        m0 = t ? b0 : d0; o0 = t ? j0 : i0;
        if (t) { b0 = b1; j0 = j1; b1 = b2; j1 = j2; }
        else   { d0 = d1; i0 = i1; d1 = d2; i1 = i2; }
        t = b0 < d0;
        m1 = t ? b0 : d0; o1 = t ? j0 : i0;
        if (t) { b0 = b1; j0 = j1; }
        else   { d0 = d1; i0 = i1; }
        t = b0 < d0;
        m2 = t ? b0 : d0; o2 = t ? j0 : i0;

        const float f0 = sqrtf(fmaxf(m0 + a2, 0.f));
        const float f1 = sqrtf(fmaxf(m1 + a2, 0.f));
        const float f2 = sqrtf(fmaxf(m2 + a2, 0.f));
        float w0 = 1.f / (f0 + 1e-10f);
        float w1 = 1.f / (f1 + 1e-10f);
        float w2 = 1.f / (f2 + 1e-10f);
        const float inv = 1.f / (w0 + w1 + w2);
        const int g = b * NPT + n;
        g_nnw4[g] = make_float4(w0 * inv, w1 * inv, w2 * inv, 0.f);
        g_nni4[g] = make_int4(o0, o1, o2, 0);
    }
}

// ---------------------------------------------------------------------------
// k_gather: warp per query; register accumulation; fp16 hi/lo out.
// ---------------------------------------------------------------------------
__global__ void __launch_bounds__(256) k_gather() {
    const int wid = threadIdx.x >> 5, lane = threadIdx.x & 31;
    const int n = blockIdx.x * 8 + wid;
    const int b = n >> 12;
    const float4 wv = g_nnw4[n];
    const int4   iv = g_nni4[n];
    const float* p2t = g_p2t + (size_t)b * SPT * D2_;
    const float4 v0 = *(const float4*)(p2t + (size_t)iv.x * D2_ + lane * 4);
    const float4 v1 = *(const float4*)(p2t + (size_t)iv.y * D2_ + lane * 4);
    const float4 v2 = *(const float4*)(p2t + (size_t)iv.z * D2_ + lane * 4);
    float4 a;
    a.x = fmaf(wv.x, v0.x, fmaf(wv.y, v1.x, wv.z * v2.x));
    a.y = fmaf(wv.x, v0.y, fmaf(wv.y, v1.y, wv.z * v2.y));
    a.z = fmaf(wv.x, v0.z, fmaf(wv.y, v1.z, wv.z * v2.z));
    a.w = fmaf(wv.x, v0.w, fmaf(wv.y, v1.w, wv.z * v2.w));
    uint32_t h0, l0, h1, l1, h2, l2, h3, l3;
    split_f16(a.x, h0, l0); split_f16(a.y, h1, l1);
    split_f16(a.z, h2, l2); split_f16(a.w, h3, l3);
    const size_t o = (size_t)n * CIN + D1_ + lane * 4;
    *(uint2*)(g_x1h + o) = make_uint2(h0 | (h1 << 16), h2 | (h3 << 16));
    *(uint2*)(g_x1l + o) = make_uint2(l0 | (l1 << 16), l2 | (l3 << 16));
}

// ---------------------------------------------------------------------------
// Warp-MMA GEMM. CTA 128(M) x 128(N), 256 threads (4Mx2N warps), K-chunk 64,
// double-buffered smem, __launch_bounds__(256,2), grid (2,512) X L2 pairing.
// LAYER 1: X split (Xh+Xl) * W  -> buffer Xh 16K | Xl 16K | W 16K = 48KB
// LAYER 2: single X * W         -> buffer Xh 16K | W 16K        = 32KB
// ---------------------------------------------------------------------------
template <int LAYER>
__global__ void __launch_bounds__(256, 2) k_mma() {
    constexpr int K  = (LAYER == 1) ? CIN : CO;
    constexpr int KT = K / 64;
    constexpr bool XL = (LAYER == 1);
    constexpr uint32_t WOFF = XL ? 32768 : 16384;
    constexpr uint32_t BUF  = XL ? 49152 : 32768;
    const __half* xh = (LAYER == 1) ? g_x1h : g_x2h;
    const __half* xl = g_x1l;
    const __half* wp = (LAYER == 1) ? g_w1 : g_w2;
    float* C = g_y1;

    extern __shared__ uint8_t dsm[];
    const uint32_t sbase = (smem_u32(dsm) + 1023) & ~1023u;

    const int tid  = threadIdx.x, wid = tid >> 5, lane = tid & 31;
    const int m0   = blockIdx.y << 7;
    const int n0   = blockIdx.x << 7;
    const int wm   = wid & 3, wn = wid >> 2;

    auto stage = [&](int kt) {
        const uint32_t base = sbase + (kt & 1) * BUF;
        const int k0 = kt * 64;
        // Xh: 1024 segs of 16B
#pragma unroll
        for (int i = 0; i < 4; i++) {
            const int q = tid + i * 256;
            const int r = q >> 3, c = q & 7;
            const __half* src = xh + (size_t)(m0 + r) * K + k0 + c * 8;
            const uint32_t dst = base + r * 128 + (((uint32_t)(c ^ (r & 7))) << 4);
            asm volatile("cp.async.cg.shared.global [%0], [%1], 16;" :: "r"(dst), "l"(src));
        }
        if (XL) {
#pragma unroll
            for (int i = 0; i < 4; i++) {
                const int q = tid + i * 256;
                const int r = q >> 3, c = q & 7;
                const __half* src = xl + (size_t)(m0 + r) * K + k0 + c * 8;
                const uint32_t dst = base + 16384 + r * 128 + (((uint32_t)(c ^ (r & 7))) << 4);
                asm volatile("cp.async.cg.shared.global [%0], [%1], 16;" :: "r"(dst), "l"(src));
            }
        }
        // W: 128 rows -> 1024 segs of 16B
#pragma unroll
        for (int i = 0; i < 4; i++) {
            const int q = tid + i * 256;
            const int r = q >> 3, c = q & 7;
            const __half* src = wp + (size_t)(n0 + r) * K + k0 + c * 8;
            const uint32_t dst = base + WOFF + r * 128 + (((uint32_t)(c ^ (r & 7))) << 4);
            asm volatile("cp.async.cg.shared.global [%0], [%1], 16;" :: "r"(dst), "l"(src));
        }
        asm volatile("cp.async.commit_group;");
    };

    int rA[2], cAx = lane >> 4;
#pragma unroll
    for (int s = 0; s < 2; s++)
        rA[s] = wm * 32 + s * 16 + (lane & 7) + ((lane >> 3) & 1) * 8;
    int rB[4], cBx = (lane >> 3) & 1;
#pragma unroll
    for (int jj = 0; jj < 4; jj++)
        rB[jj] = wn * 64 + (jj * 2 + (lane >> 4)) * 8 + (lane & 7);

    float acc[2][8][4];
#pragma unroll
    for (int s = 0; s < 2; s++)
#pragma unroll
        for (int j = 0; j < 8; j++)
#pragma unroll
            for (int v = 0; v < 4; v++) acc[s][j][v] = 0.f;

    stage(0);
#pragma unroll 1
    for (int kt = 0; kt < KT; kt++) {
        if (kt + 1 < KT) { stage(kt + 1); asm volatile("cp.async.wait_group 1;"); }
        else             { asm volatile("cp.async.wait_group 0;"); }
        __syncthreads();
        const uint32_t base = sbase + (kt & 1) * BUF;
        const uint32_t bXh = base, bXl = base + 16384, bW = base + WOFF;
#pragma unroll
        for (int ks = 0; ks < 4; ks++) {
            uint32_t ah[2][4], al[2][4], bw[4][4];
#pragma unroll
            for (int s = 0; s < 2; s++) {
                const uint32_t off = rA[s] * 128 + (((uint32_t)((ks * 2 + cAx) ^ (rA[s] & 7))) << 4);
                asm volatile("ldmatrix.sync.aligned.m8n8.x4.shared.b16 {%0,%1,%2,%3}, [%4];"
                    : "=r"(ah[s][0]), "=r"(ah[s][1]), "=r"(ah[s][2]), "=r"(ah[s][3]) : "r"(bXh + off));
                if (XL)
                    asm volatile("ldmatrix.sync.aligned.m8n8.x4.shared.b16 {%0,%1,%2,%3}, [%4];"
                        : "=r"(al[s][0]), "=r"(al[s][1]), "=r"(al[s][2]), "=r"(al[s][3]) : "r"(bXl + off));
            }
#pragma unroll
            for (int jj = 0; jj < 4; jj++) {
                const uint32_t off = rB[jj] * 128 + (((uint32_t)((ks * 2 + cBx) ^ (rB[jj] & 7))) << 4);
                asm volatile("ldmatrix.sync.aligned.m8n8.x4.shared.b16 {%0,%1,%2,%3}, [%4];"
                    : "=r"(bw[jj][0]), "=r"(bw[jj][1]), "=r"(bw[jj][2]), "=r"(bw[jj][3]) : "r"(bW + off));
            }
#define MMA_(A, Bf, CC) asm volatile( \
    "mma.sync.aligned.m16n8k16.row.col.f32.f16.f16.f32 " \
    "{%0,%1,%2,%3}, {%4,%5,%6,%7}, {%8,%9}, {%0,%1,%2,%3};" \
    : "+f"((CC)[0]), "+f"((CC)[1]), "+f"((CC)[2]), "+f"((CC)[3]) \
    : "r"((A)[0]), "r"((A)[1]), "r"((A)[2]), "r"((A)[3]), "r"((Bf)[0]), "r"((Bf)[1]))
#pragma unroll
            for (int s = 0; s < 2; s++)
#pragma unroll
                for (int j = 0; j < 8; j++)
                    MMA_(ah[s], (&bw[j >> 1][(j & 1) * 2]), acc[s][j]);
            if (XL) {
#pragma unroll
                for (int s = 0; s < 2; s++)
#pragma unroll
                    for (int j = 0; j < 8; j++)
                        MMA_(al[s], (&bw[j >> 1][(j & 1) * 2]), acc[s][j]);
            }
#undef MMA_
        }
        __syncthreads();
    }

    // ---- lean epilogue: direct fp32 stores to C[n,256] ----
#pragma unroll
    for (int s = 0; s < 2; s++) {
        const int m = m0 + wm * 32 + s * 16 + (lane >> 2);
#pragma unroll
        for (int j = 0; j < 8; j++) {
            const int n = n0 + wn * 64 + j * 8 + (lane & 3) * 2;
            *(float2*)(C + (size_t)m * CO + n)       = make_float2(acc[s][j][0], acc[s][j][1]);
            *(float2*)(C + (size_t)(m + 8) * CO + n) = make_float2(acc[s][j][2], acc[s][j][3]);
        }
    }
}

// ---------------------------------------------------------------------------
// k_stats: per-channel partials over y [n,256]; deterministic.
// ---------------------------------------------------------------------------
__global__ void __launch_bounds__(256) k_stats() {
    __shared__ float4 ss[256], qq[256];
    const int j = blockIdx.x, t = threadIdx.x;
    const int cq = t & 63, rq = t >> 6;
    const float4* y = (const float4*)g_y1;
    float4 s = make_float4(0, 0, 0, 0), q = make_float4(0, 0, 0, 0);
    for (int i = 0; i < 64; i++) {
        const int row = j * 256 + rq * 64 + i;
        const float4 v = y[(size_t)row * 64 + cq];
        s.x += v.x; s.y += v.y; s.z += v.z; s.w += v.w;
        q.x = fmaf(v.x, v.x, q.x); q.y = fmaf(v.y, v.y, q.y);
        q.z = fmaf(v.z, v.z, q.z); q.w = fmaf(v.w, v.w, q.w);
    }
    ss[t] = s; qq[t] = q;
    __syncthreads();
    if (t < 64) {
        float4 a = ss[t], b = ss[t + 64], c = ss[t + 128], d = ss[t + 192];
        float4 e = qq[t], f = qq[t + 64], g = qq[t + 128], h = qq[t + 192];
        float4 so = make_float4((a.x + b.x) + (c.x + d.x), (a.y + b.y) + (c.y + d.y),
                                (a.z + b.z) + (c.z + d.z), (a.w + b.w) + (c.w + d.w));
        float4 qo = make_float4((e.x + f.x) + (g.x + h.x), (e.y + f.y) + (g.y + h.y),
                                (e.z + f.z) + (g.z + h.z), (e.w + f.w) + (g.w + h.w));
        *(float4*)&g_psum[j * 256 + t * 4] = so;
        *(float4*)&g_psq[j * 256 + t * 4]  = qo;
    }
}

// ---------------------------------------------------------------------------
// fold: reduce 256 partials/channel -> folded BN affine
// ---------------------------------------------------------------------------
__global__ void k_fold(const float* __restrict__ gamma, const float* __restrict__ beta,
                       int layer) {
    const int c = threadIdx.x;
    float s = 0.f, q = 0.f;
    for (int j = 0; j < 256; j++) {
        s += g_psum[j * 256 + c];
        q += g_psq[j * 256 + c];
    }
    const float mean = s * (1.f / (float)NS);
    const float var  = q * (1.f / (float)NS) - mean * mean;
    const float a = gamma[c] * rsqrtf(var + 1e-5f);
    const float b = beta[c] - mean * a;
    if (layer == 1) { g_a1[c] = a; g_b1[c] = b; }
    else            { g_a2[c] = a; g_b2[c] = b; }
}

// ---------------------------------------------------------------------------
// x2 = f16(relu(a1*y1 + b1))  (single term)
// ---------------------------------------------------------------------------
__global__ void __launch_bounds__(256) k_x2() {
    const size_t i = (size_t)blockIdx.x * 256 + threadIdx.x;
    const size_t row = i >> 6;
    const int cq = (int)(i & 63), c0 = cq * 4;
    float4 v = ((const float4*)g_y1)[row * 64 + cq];
    const float4 a = *(const float4*)&g_a1[c0];
    const float4 b = *(const float4*)&g_b1[c0];
    v.x = fmaxf(fmaf(a.x, v.x, b.x), 0.f);
    v.y = fmaxf(fmaf(a.y, v.y, b.y), 0.f);
    v.z = fmaxf(fmaf(a.z, v.z, b.z), 0.f);
    v.w = fmaxf(fmaf(a.w, v.w, b.w), 0.f);
    const uint32_t h0 = (uint32_t)__half_as_ushort(__float2half_rn(v.x));
    const uint32_t h1 = (uint32_t)__half_as_ushort(__float2half_rn(v.y));
    const uint32_t h2 = (uint32_t)__half_as_ushort(__float2half_rn(v.z));
    const uint32_t h3 = (uint32_t)__half_as_ushort(__float2half_rn(v.w));
    *(uint2*)(g_x2h + row * CO + c0) = make_uint2(h0 | (h1 << 16), h2 | (h3 << 16));
}

// ---------------------------------------------------------------------------
// finalize: out[b,o,n] = relu(a2*y2[n,o] + b2)
// ---------------------------------------------------------------------------
__global__ void k_finalize(float* __restrict__ out) {
    __shared__ float t[32][33];
    const int b = blockIdx.z, o0 = blockIdx.y * 32, n0 = blockIdx.x * 32;
    const int tx = threadIdx.x, ty = threadIdx.y;
    const float a = g_a2[o0 + tx], bb = g_b2[o0 + tx];
#pragma unroll
    for (int i = 0; i < 4; i++) {
        const int n = n0 + ty + i * 8;
        const float v = g_y1[(size_t)(b * NPT + n) * CO + o0 + tx];
        t[tx][ty + i * 8] = fmaxf(fmaf(a, v, bb), 0.f);
    }
    __syncthreads();
#pragma unroll
    for (int i = 0; i < 4; i++)
        out[((size_t)b * CO + o0 + ty + i * 8) * NPT + n0 + tx] = t[ty + i * 8][tx];
}

// ---------------------------------------------------------------------------
// Launch
// ---------------------------------------------------------------------------
extern "C" void kernel_launch(void* const* d_in, const int* in_sizes, int n_in,
                              void* d_out, int out_size) {
    const float* xyz1    = (const float*)d_in[0];
    const float* xyz2    = (const float*)d_in[1];
    const float* points1 = (const float*)d_in[2];
    const float* points2 = (const float*)d_in[3];
    const float* W1      = (const float*)d_in[4];
    const float* g1      = (const float*)d_in[6];
    const float* be1     = (const float*)d_in[7];
    const float* W2      = (const float*)d_in[8];
    const float* g2      = (const float*)d_in[10];
    const float* be2     = (const float*)d_in[11];
    float* out = (float*)d_out;

    cudaFuncSetAttribute(k_mma<1>, cudaFuncAttributeMaxDynamicSharedMemorySize, 2 * 49152 + 1024);
    cudaFuncSetAttribute(k_mma<2>, cudaFuncAttributeMaxDynamicSharedMemorySize, 2 * 32768 + 1024);

    k_prep<<<19072, 256>>>(W1, W2, points2, points1);
    k_nn<<<dim3(32, 16), 256>>>(xyz1, xyz2);
    k_gather<<<8192, 256>>>();
    k_mma<1><<<dim3(2, 512), 256, 2 * 49152 + 1024>>>();
    k_stats<<<256, 256>>>();
    k_fold<<<1, 256>>>(g1, be1, 1);
    k_x2<<<16384, 256>>>();
    k_mma<2><<<dim3(2, 512), 256, 2 * 32768 + 1024>>>();
    k_stats<<<256, 256>>>();
    k_fold<<<1, 256>>>(g2, be2, 2);
    k_finalize<<<dim3(128, 8, 16), dim3(32, 8)>>>(out);
}